// round 3
// baseline (speedup 1.0000x reference)
#include <cuda_runtime.h>
#include <cstdint>
#include <cstddef>

// ---------------------------------------------------------------------------
// MultiHeadAttention fused block, fp32 SIMT baseline (round 2: static-smem).
//   q = Q@Wq^T+bq ; k = K@Wk^T+bk ; v = V@Wv^T+bv    (head-major layout)
//   ctx = softmax(q k^T / 8 + mask) v                 (flash, online softmax)
//   x   = ctx@Wo^T + bo + Q
//   out = LayerNorm(x) * gamma + beta
// ---------------------------------------------------------------------------

#define B_SZ   4
#define S_SZ   2048
#define D_SZ   1024
#define H_SZ   16
#define DH_SZ  64
#define M_SZ   (B_SZ * S_SZ)          // 8192

// Scratch (device globals: allocation-free per harness rules)
__device__ float g_q[M_SZ * D_SZ];    // head-major q; later reused as pre-LN x
__device__ float g_k[M_SZ * D_SZ];    // head-major k
__device__ float g_v[M_SZ * D_SZ];    // head-major v
__device__ float g_ctx[M_SZ * D_SZ];  // merged-head ctx, row-major (B*S, D)

// ---------------------------------------------------------------------------
// GEMM: out = A @ W^T + bias (+resid). A: (8192,1024) rm, W: (1024,1024) rm.
// BM=BN=128, BK=16, 256 threads, 8x8 micro-tile, k-major smem (pad 4).
// OUTMODE 0/1/2 -> write g_q/g_k/g_v in head-major [B,H,S,dh] layout.
// OUTMODE 3     -> A is g_ctx (param ignored), write g_q = acc + bo + resid.
// ---------------------------------------------------------------------------
template <int OUTMODE>
__global__ void __launch_bounds__(256)
gemm128x128(const float* __restrict__ A, const float* __restrict__ W,
            const float* __restrict__ bias, const float* __restrict__ resid)
{
    __shared__ float As[16 * 132];
    __shared__ float Bs[16 * 132];

    const int K   = D_SZ;
    const int m0  = blockIdx.y * 128;
    const int n0  = blockIdx.x * 128;
    const int tid = threadIdx.x;
    const int tr  = tid >> 4;          // 0..15
    const int tc  = tid & 15;          // 0..15
    const int r0  = tr * 8;
    const int c0  = tc * 8;
    const int lr  = tid >> 2;          // 0..63 (loader row)
    const int lk  = (tid & 3) << 2;    // 0,4,8,12 (loader k offset)

    const float* Asrc = (OUTMODE == 3) ? (const float*)g_ctx : A;
    const float* Ap = Asrc + (size_t)(m0 + lr) * K + lk;
    const float* Wp = W    + (size_t)(n0 + lr) * K + lk;

    float acc[8][8];
#pragma unroll
    for (int i = 0; i < 8; i++)
#pragma unroll
        for (int j = 0; j < 8; j++) acc[i][j] = 0.f;

    for (int k0 = 0; k0 < K; k0 += 16) {
        float4 a0 = *(const float4*)(Ap + k0);
        float4 a1 = *(const float4*)(Ap + (size_t)64 * K + k0);
        float4 b0 = *(const float4*)(Wp + k0);
        float4 b1 = *(const float4*)(Wp + (size_t)64 * K + k0);
        __syncthreads();   // previous iteration's compute reads finished
        As[(lk + 0) * 132 + lr] = a0.x;
        As[(lk + 1) * 132 + lr] = a0.y;
        As[(lk + 2) * 132 + lr] = a0.z;
        As[(lk + 3) * 132 + lr] = a0.w;
        As[(lk + 0) * 132 + lr + 64] = a1.x;
        As[(lk + 1) * 132 + lr + 64] = a1.y;
        As[(lk + 2) * 132 + lr + 64] = a1.z;
        As[(lk + 3) * 132 + lr + 64] = a1.w;
        Bs[(lk + 0) * 132 + lr] = b0.x;
        Bs[(lk + 1) * 132 + lr] = b0.y;
        Bs[(lk + 2) * 132 + lr] = b0.z;
        Bs[(lk + 3) * 132 + lr] = b0.w;
        Bs[(lk + 0) * 132 + lr + 64] = b1.x;
        Bs[(lk + 1) * 132 + lr + 64] = b1.y;
        Bs[(lk + 2) * 132 + lr + 64] = b1.z;
        Bs[(lk + 3) * 132 + lr + 64] = b1.w;
        __syncthreads();

#pragma unroll
        for (int kk = 0; kk < 16; kk++) {
            const float4* ap = (const float4*)(As + kk * 132 + r0);
            const float4* bp = (const float4*)(Bs + kk * 132 + c0);
            float4 av0 = ap[0], av1 = ap[1];
            float4 bv0 = bp[0], bv1 = bp[1];
            float a[8] = {av0.x, av0.y, av0.z, av0.w, av1.x, av1.y, av1.z, av1.w};
            float b[8] = {bv0.x, bv0.y, bv0.z, bv0.w, bv1.x, bv1.y, bv1.z, bv1.w};
#pragma unroll
            for (int i = 0; i < 8; i++)
#pragma unroll
                for (int j = 0; j < 8; j++)
                    acc[i][j] += a[i] * b[j];
        }
    }

    if (OUTMODE < 3) {
        float* out = (OUTMODE == 0) ? g_q : (OUTMODE == 1) ? g_k : g_v;
#pragma unroll
        for (int i = 0; i < 8; i++) {
            const int m = m0 + r0 + i;
            const int bI = m >> 11;          // / 2048
            const int s  = m & 2047;
#pragma unroll
            for (int j = 0; j < 8; j++) {
                const int n    = n0 + c0 + j;
                const int head = n >> 6;
                const int dd   = n & 63;
                const size_t dst = ((size_t)(bI * H_SZ + head) << 17)  // *S*DH
                                 + ((size_t)s << 6) + dd;
                out[dst] = acc[i][j] + bias[n];
            }
        }
    } else {
        float* out = g_q;  // reuse as pre-LN x (q fully consumed by attention)
#pragma unroll
        for (int i = 0; i < 8; i++) {
            const int m = m0 + r0 + i;
#pragma unroll
            for (int j = 0; j < 8; j++) {
                const int n = n0 + c0 + j;
                const size_t idx = (size_t)m * D_SZ + n;
                out[idx] = acc[i][j] + bias[n] + resid[idx];
            }
        }
    }
}

// ---------------------------------------------------------------------------
// Flash attention: Q tile 64 rows, KV tile 32 rows, dh=64, online softmax.
// 256 threads. S tile (64x32): 4x2 per thread. O tile (64x64): 4x4 per
// thread. Row stats (m,l) in registers; each row owned by a 16-lane shuffle
// group (same tr). Static smem only (41.5 KB) -> no attribute call needed.
// ---------------------------------------------------------------------------
#define KT 32
__global__ void __launch_bounds__(256)
flash_kernel(const int* __restrict__ mask)
{
    __shared__ float Qs[64 * 64];        // 4096
    __shared__ float Ks[KT * 65];        // 2080
    __shared__ float Vs[KT * 65];        // 2080
    __shared__ float Ps[64 * 33];        // 2112  (total 10368 f = 41472 B)

    const int b  = blockIdx.z;
    const int h  = blockIdx.y;
    const int q0 = blockIdx.x * 64;
    const int tid = threadIdx.x;
    const int tr  = tid >> 4;      // 0..15
    const int tc  = tid & 15;      // 0..15
    const int r0  = tr * 4;        // S/O rows
    const int cs0 = tc * 2;        // S cols (32 wide)
    const int co0 = tc * 4;        // O cols (64 wide, dh)

    const size_t bh = (size_t)(b * H_SZ + h) * (S_SZ * DH_SZ);

    // Load Q tile (rows contiguous in dh), vectorized
    {
        const float4* gqp = (const float4*)(g_q + bh + (size_t)q0 * DH_SZ);
        float4* qs4 = (float4*)Qs;
        for (int idx = tid; idx < 1024; idx += 256) qs4[idx] = gqp[idx];
    }
    const int* mrow = mask + b * S_SZ;

    float m_i[4], l_i[4], o[4][4];
#pragma unroll
    for (int i = 0; i < 4; i++) {
        m_i[i] = -1e30f;
        l_i[i] = 0.f;
#pragma unroll
        for (int j = 0; j < 4; j++) o[i][j] = 0.f;
    }

    for (int t = 0; t < S_SZ / KT; t++) {
        __syncthreads();   // previous tile's Ps/Vs reads done
        {
            const float4* gkp = (const float4*)(g_k + bh + (size_t)(t * KT) * DH_SZ);
            const float4* gvp = (const float4*)(g_v + bh + (size_t)(t * KT) * DH_SZ);
            for (int idx = tid; idx < KT * 16; idx += 256) {
                const int r  = idx >> 4;         // row (16 float4 per row)
                const int d4 = (idx & 15) << 2;  // col within row
                float4 kv = gkp[idx];
                float4 vv = gvp[idx];
                float* kd = Ks + r * 65 + d4;
                float* vd = Vs + r * 65 + d4;
                kd[0] = kv.x; kd[1] = kv.y; kd[2] = kv.z; kd[3] = kv.w;
                vd[0] = vv.x; vd[1] = vv.y; vd[2] = vv.z; vd[3] = vv.w;
            }
        }
        __syncthreads();

        // S = Q K^T  (64 x 32 tile, 4x2 per thread)
        float s[4][2];
#pragma unroll
        for (int i = 0; i < 4; i++) { s[i][0] = 0.f; s[i][1] = 0.f; }

#pragma unroll 8
        for (int d = 0; d < 64; d++) {
            float a[4], kb[2];
#pragma unroll
            for (int i = 0; i < 4; i++) a[i] = Qs[(r0 + i) * 64 + d];
#pragma unroll
            for (int j = 0; j < 2; j++) kb[j] = Ks[(cs0 + j) * 65 + d];
#pragma unroll
            for (int i = 0; i < 4; i++)
#pragma unroll
                for (int j = 0; j < 2; j++)
                    s[i][j] += a[i] * kb[j];
        }

        // scale + mask
        float madd[2];
#pragma unroll
        for (int j = 0; j < 2; j++)
            madd[j] = (mrow[t * KT + cs0 + j] == 0) ? -1e9f : 0.f;
#pragma unroll
        for (int i = 0; i < 4; i++)
#pragma unroll
            for (int j = 0; j < 2; j++)
                s[i][j] = s[i][j] * 0.125f + madd[j];

        // online softmax update (per-row over 16-lane group)
#pragma unroll
        for (int i = 0; i < 4; i++) {
            float rm = fmaxf(s[i][0], s[i][1]);
#pragma unroll
            for (int off = 1; off < 16; off <<= 1)
                rm = fmaxf(rm, __shfl_xor_sync(0xffffffffu, rm, off));
            const float mnew  = fmaxf(m_i[i], rm);
            const float alpha = __expf(m_i[i] - mnew);
            float rsum = 0.f;
#pragma unroll
            for (int j = 0; j < 2; j++) {
                const float p = __expf(s[i][j] - mnew);
                Ps[(r0 + i) * 33 + cs0 + j] = p;
                rsum += p;
            }
#pragma unroll
            for (int off = 1; off < 16; off <<= 1)
                rsum += __shfl_xor_sync(0xffffffffu, rsum, off);
            l_i[i] = l_i[i] * alpha + rsum;
            m_i[i] = mnew;
#pragma unroll
            for (int j = 0; j < 4; j++) o[i][j] *= alpha;
        }
        __syncthreads();   // Ps visible to all

        // O += P V  (64 x 64, 4x4 per thread, contraction over KT)
#pragma unroll 8
        for (int c = 0; c < KT; c++) {
            float a[4], vb[4];
#pragma unroll
            for (int i = 0; i < 4; i++) a[i] = Ps[(r0 + i) * 33 + c];
#pragma unroll
            for (int j = 0; j < 4; j++) vb[j] = Vs[c * 65 + co0 + j];
#pragma unroll
            for (int i = 0; i < 4; i++)
#pragma unroll
                for (int j = 0; j < 4; j++)
                    o[i][j] += a[i] * vb[j];
        }
    }

    // write ctx in merged-head row-major layout (B*S, D)
#pragma unroll
    for (int i = 0; i < 4; i++) {
        const float inv_l = 1.f / l_i[i];
        const size_t row = (size_t)(b * S_SZ + q0 + r0 + i) * D_SZ + h * DH_SZ + co0;
#pragma unroll
        for (int j = 0; j < 4; j++)
            g_ctx[row + j] = o[i][j] * inv_l;
    }
}

// ---------------------------------------------------------------------------
// LayerNorm over last dim (1024). One block per row, two-pass (exact).
// Input: g_q (holding x = ctx@Wo^T + bo + Q).
// ---------------------------------------------------------------------------
__global__ void __launch_bounds__(256)
ln_kernel(const float* __restrict__ gamma, const float* __restrict__ beta,
          float* __restrict__ out)
{
    __shared__ float red[8];
    const int row = blockIdx.x;
    const int tid = threadIdx.x;
    const float* xr = g_q + (size_t)row * D_SZ;

    float v[4];
#pragma unroll
    for (int u = 0; u < 4; u++) v[u] = xr[tid + 256 * u];

    float s = v[0] + v[1] + v[2] + v[3];
#pragma unroll
    for (int off = 16; off > 0; off >>= 1)
        s += __shfl_xor_sync(0xffffffffu, s, off);
    if ((tid & 31) == 0) red[tid >> 5] = s;
    __syncthreads();
    float tot = 0.f;
#pragma unroll
    for (int w = 0; w < 8; w++) tot += red[w];
    const float mu = tot * (1.f / 1024.f);

    float d0 = v[0] - mu, d1 = v[1] - mu, d2 = v[2] - mu, d3 = v[3] - mu;
    float ss = d0 * d0 + d1 * d1 + d2 * d2 + d3 * d3;
#pragma unroll
    for (int off = 16; off > 0; off >>= 1)
        ss += __shfl_xor_sync(0xffffffffu, ss, off);
    __syncthreads();   // red reads done before rewrite
    if ((tid & 31) == 0) red[tid >> 5] = ss;
    __syncthreads();
    float vtot = 0.f;
#pragma unroll
    for (int w = 0; w < 8; w++) vtot += red[w];
    const float inv = rsqrtf(vtot * (1.f / 1024.f) + 1e-5f);

#pragma unroll
    for (int u = 0; u < 4; u++) {
        const int c = tid + 256 * u;
        out[(size_t)row * D_SZ + c] = gamma[c] * (v[u] - mu) * inv + beta[c];
    }
}

// ---------------------------------------------------------------------------
extern "C" void kernel_launch(void* const* d_in, const int* in_sizes, int n_in,
                              void* d_out, int out_size)
{
    const float* Q     = (const float*)d_in[0];
    const float* K     = (const float*)d_in[1];
    const float* V     = (const float*)d_in[2];
    const int*   mask  = (const int*)  d_in[3];
    const float* Wq    = (const float*)d_in[4];
    const float* bq    = (const float*)d_in[5];
    const float* Wk    = (const float*)d_in[6];
    const float* bk    = (const float*)d_in[7];
    const float* Wv    = (const float*)d_in[8];
    const float* bv    = (const float*)d_in[9];
    const float* Wo    = (const float*)d_in[10];
    const float* bo    = (const float*)d_in[11];
    const float* gamma = (const float*)d_in[12];
    const float* beta  = (const float*)d_in[13];
    float* out = (float*)d_out;

    const dim3 gemm_grid(D_SZ / 128, M_SZ / 128);   // (8, 64)

    gemm128x128<0><<<gemm_grid, 256>>>(Q, Wq, bq, nullptr);
    gemm128x128<1><<<gemm_grid, 256>>>(K, Wk, bk, nullptr);
    gemm128x128<2><<<gemm_grid, 256>>>(V, Wv, bv, nullptr);

    flash_kernel<<<dim3(S_SZ / 64, H_SZ, B_SZ), 256>>>(mask);

    gemm128x128<3><<<gemm_grid, 256>>>(nullptr, Wo, bo, Q);

    ln_kernel<<<M_SZ, 256>>>(gamma, beta, out);
}

// round 4
// speedup vs baseline: 1.4708x; 1.4708x over previous
#include <cuda_runtime.h>
#include <cstdint>
#include <cstddef>

// ---------------------------------------------------------------------------
// MultiHeadAttention fused block (round 3: tf32 mma.sync projection GEMMs).
//   q = Q@Wq^T+bq ; k = K@Wk^T+bk ; v = V@Wv^T+bv    (head-major layout)
//   ctx = softmax(q k^T / 8 + mask) v                 (flash SIMT, unchanged)
//   x   = ctx@Wo^T + bo + Q
//   out = LayerNorm(x) * gamma + beta
// ---------------------------------------------------------------------------

#define B_SZ   4
#define S_SZ   2048
#define D_SZ   1024
#define H_SZ   16
#define DH_SZ  64
#define M_SZ   (B_SZ * S_SZ)          // 8192

// Scratch (device globals: allocation-free per harness rules)
__device__ float g_q[M_SZ * D_SZ];    // head-major q; later reused as pre-LN x
__device__ float g_k[M_SZ * D_SZ];    // head-major k
__device__ float g_v[M_SZ * D_SZ];    // head-major v
__device__ float g_ctx[M_SZ * D_SZ];  // merged-head ctx, row-major (B*S, D)

__device__ __forceinline__ uint32_t f2tf32(float x) {
    uint32_t r;
    asm("cvt.rna.tf32.f32 %0, %1;" : "=r"(r) : "f"(x));
    return r;
}

__device__ __forceinline__ void mma16n8k8(float c[4], const uint32_t a[4],
                                          const uint32_t b[2]) {
    asm volatile(
        "mma.sync.aligned.m16n8k8.row.col.f32.tf32.tf32.f32 "
        "{%0,%1,%2,%3}, {%4,%5,%6,%7}, {%8,%9}, {%0,%1,%2,%3};\n"
        : "+f"(c[0]), "+f"(c[1]), "+f"(c[2]), "+f"(c[3])
        : "r"(a[0]), "r"(a[1]), "r"(a[2]), "r"(a[3]), "r"(b[0]), "r"(b[1]));
}

// ---------------------------------------------------------------------------
// tf32 tensor-core GEMM: out = A @ W^T + bias (+resid).
// A: (8192,1024) rm, W: (1024,1024) rm. BM=BN=128, BK=32, 256 thr (8 warps,
// 2x4 warp grid, 64x32 warp tile, 4x4 m16n8k8 tiles/warp).
// OUTMODE 0/1/2 -> write g_q/g_k/g_v in head-major [B,H,S,dh] layout.
// OUTMODE 3     -> A is g_ctx (param ignored), write g_q = acc + bo + resid.
// ---------------------------------------------------------------------------
template <int OUTMODE>
__global__ void __launch_bounds__(256, 1)
gemm_tf32(const float* __restrict__ A, const float* __restrict__ W,
          const float* __restrict__ bias, const float* __restrict__ resid)
{
    __shared__ uint32_t As[128][36];   // 18 KB, stride 36 words (conflict-free)
    __shared__ uint32_t Bs[128][36];   // 18 KB

    const int tid  = threadIdx.x;
    const int lane = tid & 31;
    const int warp = tid >> 5;
    const int wm   = (warp & 1) * 64;   // warp row offset in tile
    const int wn   = (warp >> 1) * 32;  // warp col offset in tile
    const int g    = lane >> 2;         // groupID (0..7)
    const int tg   = lane & 3;          // thread-in-group (0..3)

    const int m0 = blockIdx.y * 128;
    const int n0 = blockIdx.x * 128;

    // Loader mapping: thread covers rows lr, lr+32, lr+64, lr+96 at col lc.
    const int lr = tid >> 3;            // 0..31
    const int lc = (tid & 7) << 2;      // 0,4,...,28

    const float* Asrc = (OUTMODE == 3) ? (const float*)g_ctx : A;

    float acc[4][4][4];
#pragma unroll
    for (int mi = 0; mi < 4; mi++)
#pragma unroll
        for (int ni = 0; ni < 4; ni++)
#pragma unroll
            for (int c = 0; c < 4; c++) acc[mi][ni][c] = 0.f;

    float4 av[4], bv[4];
    // prefetch k0 = 0
#pragma unroll
    for (int u = 0; u < 4; u++) {
        av[u] = *(const float4*)(Asrc + (size_t)(m0 + lr + 32 * u) * D_SZ + lc);
        bv[u] = *(const float4*)(W    + (size_t)(n0 + lr + 32 * u) * D_SZ + lc);
    }

    for (int k0 = 0; k0 < D_SZ; k0 += 32) {
        __syncthreads();   // previous iteration's fragment reads done
#pragma unroll
        for (int u = 0; u < 4; u++) {
            uint4 pa = make_uint4(f2tf32(av[u].x), f2tf32(av[u].y),
                                  f2tf32(av[u].z), f2tf32(av[u].w));
            uint4 pb = make_uint4(f2tf32(bv[u].x), f2tf32(bv[u].y),
                                  f2tf32(bv[u].z), f2tf32(bv[u].w));
            *(uint4*)&As[lr + 32 * u][lc] = pa;
            *(uint4*)&Bs[lr + 32 * u][lc] = pb;
        }
        __syncthreads();

        if (k0 + 32 < D_SZ) {   // prefetch next tile (hides DRAM under mma)
            const int kn = k0 + 32;
#pragma unroll
            for (int u = 0; u < 4; u++) {
                av[u] = *(const float4*)(Asrc + (size_t)(m0 + lr + 32 * u) * D_SZ + kn + lc);
                bv[u] = *(const float4*)(W    + (size_t)(n0 + lr + 32 * u) * D_SZ + kn + lc);
            }
        }

#pragma unroll
        for (int kk = 0; kk < 32; kk += 8) {
            uint32_t af[4][4], bf[4][2];
#pragma unroll
            for (int mi = 0; mi < 4; mi++) {
                const int r = wm + mi * 16 + g;
                af[mi][0] = As[r    ][kk + tg];
                af[mi][1] = As[r + 8][kk + tg];
                af[mi][2] = As[r    ][kk + tg + 4];
                af[mi][3] = As[r + 8][kk + tg + 4];
            }
#pragma unroll
            for (int ni = 0; ni < 4; ni++) {
                const int c = wn + ni * 8 + g;
                bf[ni][0] = Bs[c][kk + tg];
                bf[ni][1] = Bs[c][kk + tg + 4];
            }
#pragma unroll
            for (int mi = 0; mi < 4; mi++)
#pragma unroll
                for (int ni = 0; ni < 4; ni++)
                    mma16n8k8(acc[mi][ni], af[mi], bf[ni]);
        }
    }

    // Epilogue. C frag (m16n8 f32): c0=(g,2tg) c1=(g,2tg+1) c2=(g+8,2tg) c3=(g+8,2tg+1)
    if (OUTMODE < 3) {
        float* out = (OUTMODE == 0) ? g_q : (OUTMODE == 1) ? g_k : g_v;
#pragma unroll
        for (int mi = 0; mi < 4; mi++)
#pragma unroll
            for (int ni = 0; ni < 4; ni++)
#pragma unroll
                for (int h = 0; h < 2; h++) {
                    const int m = m0 + wm + mi * 16 + g + h * 8;
                    const int n = n0 + wn + ni * 8 + tg * 2;
                    const int bI = m >> 11, s = m & 2047;
                    const int head = n >> 6, dd = n & 63;
                    float2 val;
                    val.x = acc[mi][ni][h * 2 + 0] + bias[n];
                    val.y = acc[mi][ni][h * 2 + 1] + bias[n + 1];
                    *(float2*)&out[((size_t)(bI * H_SZ + head) << 17)
                                   + ((size_t)s << 6) + dd] = val;
                }
    } else {
        float* out = g_q;   // reuse as pre-LN x
#pragma unroll
        for (int mi = 0; mi < 4; mi++)
#pragma unroll
            for (int ni = 0; ni < 4; ni++)
#pragma unroll
                for (int h = 0; h < 2; h++) {
                    const int m = m0 + wm + mi * 16 + g + h * 8;
                    const int n = n0 + wn + ni * 8 + tg * 2;
                    const size_t idx = (size_t)m * D_SZ + n;
                    const float2 r2 = *(const float2*)&resid[idx];
                    float2 val;
                    val.x = acc[mi][ni][h * 2 + 0] + bias[n]     + r2.x;
                    val.y = acc[mi][ni][h * 2 + 1] + bias[n + 1] + r2.y;
                    *(float2*)&out[idx] = val;
                }
    }
}

// ---------------------------------------------------------------------------
// Flash attention: Q tile 64 rows, KV tile 32 rows, dh=64, online softmax.
// 256 threads. (Unchanged from round 2.)
// ---------------------------------------------------------------------------
#define KT 32
__global__ void __launch_bounds__(256)
flash_kernel(const int* __restrict__ mask)
{
    __shared__ float Qs[64 * 64];        // 4096
    __shared__ float Ks[KT * 65];        // 2080
    __shared__ float Vs[KT * 65];        // 2080
    __shared__ float Ps[64 * 33];        // 2112  (total 41472 B)

    const int b  = blockIdx.z;
    const int h  = blockIdx.y;
    const int q0 = blockIdx.x * 64;
    const int tid = threadIdx.x;
    const int tr  = tid >> 4;      // 0..15
    const int tc  = tid & 15;      // 0..15
    const int r0  = tr * 4;        // S/O rows
    const int cs0 = tc * 2;        // S cols (32 wide)
    const int co0 = tc * 4;        // O cols (64 wide, dh)

    const size_t bh = (size_t)(b * H_SZ + h) * (S_SZ * DH_SZ);

    {
        const float4* gqp = (const float4*)(g_q + bh + (size_t)q0 * DH_SZ);
        float4* qs4 = (float4*)Qs;
        for (int idx = tid; idx < 1024; idx += 256) qs4[idx] = gqp[idx];
    }
    const int* mrow = mask + b * S_SZ;

    float m_i[4], l_i[4], o[4][4];
#pragma unroll
    for (int i = 0; i < 4; i++) {
        m_i[i] = -1e30f;
        l_i[i] = 0.f;
#pragma unroll
        for (int j = 0; j < 4; j++) o[i][j] = 0.f;
    }

    for (int t = 0; t < S_SZ / KT; t++) {
        __syncthreads();
        {
            const float4* gkp = (const float4*)(g_k + bh + (size_t)(t * KT) * DH_SZ);
            const float4* gvp = (const float4*)(g_v + bh + (size_t)(t * KT) * DH_SZ);
            for (int idx = tid; idx < KT * 16; idx += 256) {
                const int r  = idx >> 4;
                const int d4 = (idx & 15) << 2;
                float4 kv = gkp[idx];
                float4 vv = gvp[idx];
                float* kd = Ks + r * 65 + d4;
                float* vd = Vs + r * 65 + d4;
                kd[0] = kv.x; kd[1] = kv.y; kd[2] = kv.z; kd[3] = kv.w;
                vd[0] = vv.x; vd[1] = vv.y; vd[2] = vv.z; vd[3] = vv.w;
            }
        }
        __syncthreads();

        float s[4][2];
#pragma unroll
        for (int i = 0; i < 4; i++) { s[i][0] = 0.f; s[i][1] = 0.f; }

#pragma unroll 8
        for (int d = 0; d < 64; d++) {
            float a[4], kb[2];
#pragma unroll
            for (int i = 0; i < 4; i++) a[i] = Qs[(r0 + i) * 64 + d];
#pragma unroll
            for (int j = 0; j < 2; j++) kb[j] = Ks[(cs0 + j) * 65 + d];
#pragma unroll
            for (int i = 0; i < 4; i++)
#pragma unroll
                for (int j = 0; j < 2; j++)
                    s[i][j] += a[i] * kb[j];
        }

        float madd[2];
#pragma unroll
        for (int j = 0; j < 2; j++)
            madd[j] = (mrow[t * KT + cs0 + j] == 0) ? -1e9f : 0.f;
#pragma unroll
        for (int i = 0; i < 4; i++)
#pragma unroll
            for (int j = 0; j < 2; j++)
                s[i][j] = s[i][j] * 0.125f + madd[j];

#pragma unroll
        for (int i = 0; i < 4; i++) {
            float rm = fmaxf(s[i][0], s[i][1]);
#pragma unroll
            for (int off = 1; off < 16; off <<= 1)
                rm = fmaxf(rm, __shfl_xor_sync(0xffffffffu, rm, off));
            const float mnew  = fmaxf(m_i[i], rm);
            const float alpha = __expf(m_i[i] - mnew);
            float rsum = 0.f;
#pragma unroll
            for (int j = 0; j < 2; j++) {
                const float p = __expf(s[i][j] - mnew);
                Ps[(r0 + i) * 33 + cs0 + j] = p;
                rsum += p;
            }
#pragma unroll
            for (int off = 1; off < 16; off <<= 1)
                rsum += __shfl_xor_sync(0xffffffffu, rsum, off);
            l_i[i] = l_i[i] * alpha + rsum;
            m_i[i] = mnew;
#pragma unroll
            for (int j = 0; j < 4; j++) o[i][j] *= alpha;
        }
        __syncthreads();

#pragma unroll 8
        for (int c = 0; c < KT; c++) {
            float a[4], vb[4];
#pragma unroll
            for (int i = 0; i < 4; i++) a[i] = Ps[(r0 + i) * 33 + c];
#pragma unroll
            for (int j = 0; j < 4; j++) vb[j] = Vs[c * 65 + co0 + j];
#pragma unroll
            for (int i = 0; i < 4; i++)
#pragma unroll
                for (int j = 0; j < 4; j++)
                    o[i][j] += a[i] * vb[j];
        }
    }

#pragma unroll
    for (int i = 0; i < 4; i++) {
        const float inv_l = 1.f / l_i[i];
        const size_t row = (size_t)(b * S_SZ + q0 + r0 + i) * D_SZ + h * DH_SZ + co0;
#pragma unroll
        for (int j = 0; j < 4; j++)
            g_ctx[row + j] = o[i][j] * inv_l;
    }
}

// ---------------------------------------------------------------------------
// LayerNorm over last dim (1024). One block per row, two-pass (exact).
// ---------------------------------------------------------------------------
__global__ void __launch_bounds__(256)
ln_kernel(const float* __restrict__ gamma, const float* __restrict__ beta,
          float* __restrict__ out)
{
    __shared__ float red[8];
    const int row = blockIdx.x;
    const int tid = threadIdx.x;
    const float* xr = g_q + (size_t)row * D_SZ;

    float v[4];
#pragma unroll
    for (int u = 0; u < 4; u++) v[u] = xr[tid + 256 * u];

    float s = v[0] + v[1] + v[2] + v[3];
#pragma unroll
    for (int off = 16; off > 0; off >>= 1)
        s += __shfl_xor_sync(0xffffffffu, s, off);
    if ((tid & 31) == 0) red[tid >> 5] = s;
    __syncthreads();
    float tot = 0.f;
#pragma unroll
    for (int w = 0; w < 8; w++) tot += red[w];
    const float mu = tot * (1.f / 1024.f);

    float d0 = v[0] - mu, d1 = v[1] - mu, d2 = v[2] - mu, d3 = v[3] - mu;
    float ss = d0 * d0 + d1 * d1 + d2 * d2 + d3 * d3;
#pragma unroll
    for (int off = 16; off > 0; off >>= 1)
        ss += __shfl_xor_sync(0xffffffffu, ss, off);
    __syncthreads();
    if ((tid & 31) == 0) red[tid >> 5] = ss;
    __syncthreads();
    float vtot = 0.f;
#pragma unroll
    for (int w = 0; w < 8; w++) vtot += red[w];
    const float inv = rsqrtf(vtot * (1.f / 1024.f) + 1e-5f);

#pragma unroll
    for (int u = 0; u < 4; u++) {
        const int c = tid + 256 * u;
        out[(size_t)row * D_SZ + c] = gamma[c] * (v[u] - mu) * inv + beta[c];
    }
}

// ---------------------------------------------------------------------------
extern "C" void kernel_launch(void* const* d_in, const int* in_sizes, int n_in,
                              void* d_out, int out_size)
{
    const float* Q     = (const float*)d_in[0];
    const float* K     = (const float*)d_in[1];
    const float* V     = (const float*)d_in[2];
    const int*   mask  = (const int*)  d_in[3];
    const float* Wq    = (const float*)d_in[4];
    const float* bq    = (const float*)d_in[5];
    const float* Wk    = (const float*)d_in[6];
    const float* bk    = (const float*)d_in[7];
    const float* Wv    = (const float*)d_in[8];
    const float* bv    = (const float*)d_in[9];
    const float* Wo    = (const float*)d_in[10];
    const float* bo    = (const float*)d_in[11];
    const float* gamma = (const float*)d_in[12];
    const float* beta  = (const float*)d_in[13];
    float* out = (float*)d_out;

    const dim3 gemm_grid(D_SZ / 128, M_SZ / 128);   // (8, 64)

    gemm_tf32<0><<<gemm_grid, 256>>>(Q, Wq, bq, nullptr);
    gemm_tf32<1><<<gemm_grid, 256>>>(K, Wk, bk, nullptr);
    gemm_tf32<2><<<gemm_grid, 256>>>(V, Wv, bv, nullptr);

    flash_kernel<<<dim3(S_SZ / 64, H_SZ, B_SZ), 256>>>(mask);

    gemm_tf32<3><<<gemm_grid, 256>>>(nullptr, Wo, bo, Q);

    ln_kernel<<<M_SZ, 256>>>(gamma, beta, out);
}

// round 5
// speedup vs baseline: 2.5712x; 1.7482x over previous
#include <cuda_runtime.h>
#include <cstdint>
#include <cstddef>

// ---------------------------------------------------------------------------
// MultiHeadAttention fused block (round 4: tf32 mma flash attention).
//   q = Q@Wq^T+bq ; k = K@Wk^T+bk ; v = V@Wv^T+bv    (head-major layout)
//   ctx = softmax(q k^T / 8 + mask) v                 (flash, tf32 mma)
//   x   = ctx@Wo^T + bo + Q
//   out = LayerNorm(x) * gamma + beta
// ---------------------------------------------------------------------------

#define B_SZ   4
#define S_SZ   2048
#define D_SZ   1024
#define H_SZ   16
#define DH_SZ  64
#define M_SZ   (B_SZ * S_SZ)          // 8192

__device__ float g_q[M_SZ * D_SZ];    // head-major q; later reused as pre-LN x
__device__ float g_k[M_SZ * D_SZ];    // head-major k
__device__ float g_v[M_SZ * D_SZ];    // head-major v
__device__ float g_ctx[M_SZ * D_SZ];  // merged-head ctx, row-major (B*S, D)

__device__ __forceinline__ uint32_t f2tf32(float x) {
    uint32_t r;
    asm("cvt.rna.tf32.f32 %0, %1;" : "=r"(r) : "f"(x));
    return r;
}

__device__ __forceinline__ void mma16n8k8(float c[4], const uint32_t a[4],
                                          const uint32_t b[2]) {
    asm volatile(
        "mma.sync.aligned.m16n8k8.row.col.f32.tf32.tf32.f32 "
        "{%0,%1,%2,%3}, {%4,%5,%6,%7}, {%8,%9}, {%0,%1,%2,%3};\n"
        : "+f"(c[0]), "+f"(c[1]), "+f"(c[2]), "+f"(c[3])
        : "r"(a[0]), "r"(a[1]), "r"(a[2]), "r"(a[3]), "r"(b[0]), "r"(b[1]));
}

// ---------------------------------------------------------------------------
// tf32 tensor-core GEMM (unchanged from round 3).
// ---------------------------------------------------------------------------
template <int OUTMODE>
__global__ void __launch_bounds__(256, 1)
gemm_tf32(const float* __restrict__ A, const float* __restrict__ W,
          const float* __restrict__ bias, const float* __restrict__ resid)
{
    __shared__ uint32_t As[128][36];
    __shared__ uint32_t Bs[128][36];

    const int tid  = threadIdx.x;
    const int lane = tid & 31;
    const int warp = tid >> 5;
    const int wm   = (warp & 1) * 64;
    const int wn   = (warp >> 1) * 32;
    const int g    = lane >> 2;
    const int tg   = lane & 3;

    const int m0 = blockIdx.y * 128;
    const int n0 = blockIdx.x * 128;

    const int lr = tid >> 3;
    const int lc = (tid & 7) << 2;

    const float* Asrc = (OUTMODE == 3) ? (const float*)g_ctx : A;

    float acc[4][4][4];
#pragma unroll
    for (int mi = 0; mi < 4; mi++)
#pragma unroll
        for (int ni = 0; ni < 4; ni++)
#pragma unroll
            for (int c = 0; c < 4; c++) acc[mi][ni][c] = 0.f;

    float4 av[4], bv[4];
#pragma unroll
    for (int u = 0; u < 4; u++) {
        av[u] = *(const float4*)(Asrc + (size_t)(m0 + lr + 32 * u) * D_SZ + lc);
        bv[u] = *(const float4*)(W    + (size_t)(n0 + lr + 32 * u) * D_SZ + lc);
    }

    for (int k0 = 0; k0 < D_SZ; k0 += 32) {
        __syncthreads();
#pragma unroll
        for (int u = 0; u < 4; u++) {
            uint4 pa = make_uint4(f2tf32(av[u].x), f2tf32(av[u].y),
                                  f2tf32(av[u].z), f2tf32(av[u].w));
            uint4 pb = make_uint4(f2tf32(bv[u].x), f2tf32(bv[u].y),
                                  f2tf32(bv[u].z), f2tf32(bv[u].w));
            *(uint4*)&As[lr + 32 * u][lc] = pa;
            *(uint4*)&Bs[lr + 32 * u][lc] = pb;
        }
        __syncthreads();

        if (k0 + 32 < D_SZ) {
            const int kn = k0 + 32;
#pragma unroll
            for (int u = 0; u < 4; u++) {
                av[u] = *(const float4*)(Asrc + (size_t)(m0 + lr + 32 * u) * D_SZ + kn + lc);
                bv[u] = *(const float4*)(W    + (size_t)(n0 + lr + 32 * u) * D_SZ + kn + lc);
            }
        }

#pragma unroll
        for (int kk = 0; kk < 32; kk += 8) {
            uint32_t af[4][4], bf[4][2];
#pragma unroll
            for (int mi = 0; mi < 4; mi++) {
                const int r = wm + mi * 16 + g;
                af[mi][0] = As[r    ][kk + tg];
                af[mi][1] = As[r + 8][kk + tg];
                af[mi][2] = As[r    ][kk + tg + 4];
                af[mi][3] = As[r + 8][kk + tg + 4];
            }
#pragma unroll
            for (int ni = 0; ni < 4; ni++) {
                const int c = wn + ni * 8 + g;
                bf[ni][0] = Bs[c][kk + tg];
                bf[ni][1] = Bs[c][kk + tg + 4];
            }
#pragma unroll
            for (int mi = 0; mi < 4; mi++)
#pragma unroll
                for (int ni = 0; ni < 4; ni++)
                    mma16n8k8(acc[mi][ni], af[mi], bf[ni]);
        }
    }

    if (OUTMODE < 3) {
        float* out = (OUTMODE == 0) ? g_q : (OUTMODE == 1) ? g_k : g_v;
#pragma unroll
        for (int mi = 0; mi < 4; mi++)
#pragma unroll
            for (int ni = 0; ni < 4; ni++)
#pragma unroll
                for (int h = 0; h < 2; h++) {
                    const int m = m0 + wm + mi * 16 + g + h * 8;
                    const int n = n0 + wn + ni * 8 + tg * 2;
                    const int bI = m >> 11, s = m & 2047;
                    const int head = n >> 6, dd = n & 63;
                    float2 val;
                    val.x = acc[mi][ni][h * 2 + 0] + bias[n];
                    val.y = acc[mi][ni][h * 2 + 1] + bias[n + 1];
                    *(float2*)&out[((size_t)(bI * H_SZ + head) << 17)
                                   + ((size_t)s << 6) + dd] = val;
                }
    } else {
        float* out = g_q;
#pragma unroll
        for (int mi = 0; mi < 4; mi++)
#pragma unroll
            for (int ni = 0; ni < 4; ni++)
#pragma unroll
                for (int h = 0; h < 2; h++) {
                    const int m = m0 + wm + mi * 16 + g + h * 8;
                    const int n = n0 + wn + ni * 8 + tg * 2;
                    const size_t idx = (size_t)m * D_SZ + n;
                    const float2 r2 = *(const float2*)&resid[idx];
                    float2 val;
                    val.x = acc[mi][ni][h * 2 + 0] + bias[n]     + r2.x;
                    val.y = acc[mi][ni][h * 2 + 1] + bias[n + 1] + r2.y;
                    *(float2*)&out[idx] = val;
                }
    }
}

// ---------------------------------------------------------------------------
// Flash attention with tf32 mma. 128 threads (4 warps), Q tile 64 rows,
// KV tile 64. Warp w owns q rows [16w, 16w+16). Q and P fragments stay in
// registers; online softmax on C-fragment layout with quad-lane shuffles;
// C->A fragment transpose via shfl.idx (no smem round trip for P).
// ---------------------------------------------------------------------------
__global__ void __launch_bounds__(128)
flash_mma(const int* __restrict__ mask)
{
    __shared__ uint32_t Ks[64][66];   // K tile [kv][d], tf32  (16.5 KB)
    __shared__ uint32_t Vs[64][66];   // V tile [kv][d], tf32  (16.5 KB)

    const int b    = blockIdx.z;
    const int h    = blockIdx.y;
    const int q0   = blockIdx.x * 64;
    const int tid  = threadIdx.x;
    const int lane = tid & 31;
    const int warp = tid >> 5;
    const int g    = lane >> 2;       // 0..7
    const int tg   = lane & 3;        // 0..3

    const size_t bh = (size_t)(b * H_SZ + h) * (S_SZ * DH_SZ);

    // Stage Q tile through Ks (raw float bits), extract tf32 frags * 0.125.
    {
        const float4* gq = (const float4*)(g_q + bh + (size_t)q0 * DH_SZ);
        for (int idx = tid; idx < 1024; idx += 128) {
            float4 v = gq[idx];
            const int r = idx >> 4, c = (idx & 15) << 2;
            Ks[r][c + 0] = __float_as_uint(v.x);
            Ks[r][c + 1] = __float_as_uint(v.y);
            Ks[r][c + 2] = __float_as_uint(v.z);
            Ks[r][c + 3] = __float_as_uint(v.w);
        }
    }
    __syncthreads();

    uint32_t qf[8][4];
    {
        const int r = warp * 16 + g;
#pragma unroll
        for (int k8 = 0; k8 < 8; k8++) {
            const int k = k8 * 8;
            qf[k8][0] = f2tf32(0.125f * __uint_as_float(Ks[r    ][k + tg]));
            qf[k8][1] = f2tf32(0.125f * __uint_as_float(Ks[r + 8][k + tg]));
            qf[k8][2] = f2tf32(0.125f * __uint_as_float(Ks[r    ][k + tg + 4]));
            qf[k8][3] = f2tf32(0.125f * __uint_as_float(Ks[r + 8][k + tg + 4]));
        }
    }

    float of[8][4];
#pragma unroll
    for (int ni = 0; ni < 8; ni++)
#pragma unroll
        for (int c = 0; c < 4; c++) of[ni][c] = 0.f;
    float m0 = -1e30f, m1 = -1e30f, l0 = 0.f, l1 = 0.f;

    const int* mrow = mask + b * S_SZ;

    for (int t = 0; t < S_SZ / 64; t++) {
        __syncthreads();   // prior tile's Ks/Vs reads (and Q extract) done
        {
            const float4* gk = (const float4*)(g_k + bh + (size_t)(t * 64) * DH_SZ);
            const float4* gv = (const float4*)(g_v + bh + (size_t)(t * 64) * DH_SZ);
            for (int idx = tid; idx < 1024; idx += 128) {
                const int r = idx >> 4, c = (idx & 15) << 2;
                float4 kv = gk[idx];
                float4 vv = gv[idx];
                Ks[r][c + 0] = f2tf32(kv.x);
                Ks[r][c + 1] = f2tf32(kv.y);
                Ks[r][c + 2] = f2tf32(kv.z);
                Ks[r][c + 3] = f2tf32(kv.w);
                Vs[r][c + 0] = f2tf32(vv.x);
                Vs[r][c + 1] = f2tf32(vv.y);
                Vs[r][c + 2] = f2tf32(vv.z);
                Vs[r][c + 3] = f2tf32(vv.w);
            }
        }
        __syncthreads();

        // S = (Q/8) K^T  -- 8 n-tiles of m16n8, contraction over dh=64
        float s_[8][4];
#pragma unroll
        for (int nt = 0; nt < 8; nt++) {
            s_[nt][0] = 0.f; s_[nt][1] = 0.f; s_[nt][2] = 0.f; s_[nt][3] = 0.f;
#pragma unroll
            for (int k8 = 0; k8 < 8; k8++) {
                uint32_t bf[2];
                bf[0] = Ks[nt * 8 + g][k8 * 8 + tg];
                bf[1] = Ks[nt * 8 + g][k8 * 8 + tg + 4];
                mma16n8k8(s_[nt], qf[k8], bf);
            }
        }

        // mask (additive)
#pragma unroll
        for (int nt = 0; nt < 8; nt++) {
            const int mc = t * 64 + nt * 8 + tg * 2;
            const float ma = (mrow[mc]     == 0) ? -1e9f : 0.f;
            const float mb = (mrow[mc + 1] == 0) ? -1e9f : 0.f;
            s_[nt][0] += ma; s_[nt][1] += mb;
            s_[nt][2] += ma; s_[nt][3] += mb;
        }

        // online softmax: rows g (c0,c1) and g+8 (c2,c3), quad-lane reduce
        float rm0 = -1e30f, rm1 = -1e30f;
#pragma unroll
        for (int nt = 0; nt < 8; nt++) {
            rm0 = fmaxf(rm0, fmaxf(s_[nt][0], s_[nt][1]));
            rm1 = fmaxf(rm1, fmaxf(s_[nt][2], s_[nt][3]));
        }
        rm0 = fmaxf(rm0, __shfl_xor_sync(0xffffffffu, rm0, 1));
        rm0 = fmaxf(rm0, __shfl_xor_sync(0xffffffffu, rm0, 2));
        rm1 = fmaxf(rm1, __shfl_xor_sync(0xffffffffu, rm1, 1));
        rm1 = fmaxf(rm1, __shfl_xor_sync(0xffffffffu, rm1, 2));

        const float mn0 = fmaxf(m0, rm0);
        const float mn1 = fmaxf(m1, rm1);
        const float al0 = __expf(m0 - mn0);
        const float al1 = __expf(m1 - mn1);
        m0 = mn0; m1 = mn1;

        float rs0 = 0.f, rs1 = 0.f;
#pragma unroll
        for (int nt = 0; nt < 8; nt++) {
            s_[nt][0] = __expf(s_[nt][0] - mn0);
            s_[nt][1] = __expf(s_[nt][1] - mn0);
            s_[nt][2] = __expf(s_[nt][2] - mn1);
            s_[nt][3] = __expf(s_[nt][3] - mn1);
            rs0 += s_[nt][0] + s_[nt][1];
            rs1 += s_[nt][2] + s_[nt][3];
        }
        rs0 += __shfl_xor_sync(0xffffffffu, rs0, 1);
        rs0 += __shfl_xor_sync(0xffffffffu, rs0, 2);
        rs1 += __shfl_xor_sync(0xffffffffu, rs1, 1);
        rs1 += __shfl_xor_sync(0xffffffffu, rs1, 2);
        l0 = l0 * al0 + rs0;
        l1 = l1 * al1 + rs1;

#pragma unroll
        for (int ni = 0; ni < 8; ni++) {
            of[ni][0] *= al0; of[ni][1] *= al0;
            of[ni][2] *= al1; of[ni][3] *= al1;
        }

        // O += P V : per kv-block j, transpose C-frag -> A-frag via shuffles
        const int srcA = (lane & ~3) | (tg >> 1);
        const int srcB = srcA + 2;
        const bool odd = (tg & 1);
#pragma unroll
        for (int j = 0; j < 8; j++) {
            const float x0 = __shfl_sync(0xffffffffu, s_[j][0], srcA);
            const float x1 = __shfl_sync(0xffffffffu, s_[j][1], srcA);
            const float y0 = __shfl_sync(0xffffffffu, s_[j][2], srcA);
            const float y1 = __shfl_sync(0xffffffffu, s_[j][3], srcA);
            const float x2 = __shfl_sync(0xffffffffu, s_[j][0], srcB);
            const float x3 = __shfl_sync(0xffffffffu, s_[j][1], srcB);
            const float y2 = __shfl_sync(0xffffffffu, s_[j][2], srcB);
            const float y3 = __shfl_sync(0xffffffffu, s_[j][3], srcB);
            uint32_t pa[4];
            pa[0] = f2tf32(odd ? x1 : x0);
            pa[1] = f2tf32(odd ? y1 : y0);
            pa[2] = f2tf32(odd ? x3 : x2);
            pa[3] = f2tf32(odd ? y3 : y2);
#pragma unroll
            for (int ni = 0; ni < 8; ni++) {
                uint32_t bf[2];
                bf[0] = Vs[j * 8 + tg    ][ni * 8 + g];
                bf[1] = Vs[j * 8 + tg + 4][ni * 8 + g];
                mma16n8k8(of[ni], pa, bf);
            }
        }
    }

    // epilogue: ctx in merged-head row-major (B*S, D)
    const float il0 = 1.f / l0;
    const float il1 = 1.f / l1;
    const int row0 = b * S_SZ + q0 + warp * 16 + g;
    const int colb = h * DH_SZ;
#pragma unroll
    for (int ni = 0; ni < 8; ni++) {
        const int col = colb + ni * 8 + tg * 2;
        float2 v0, v1;
        v0.x = of[ni][0] * il0; v0.y = of[ni][1] * il0;
        v1.x = of[ni][2] * il1; v1.y = of[ni][3] * il1;
        *(float2*)&g_ctx[(size_t)row0 * D_SZ + col]       = v0;
        *(float2*)&g_ctx[(size_t)(row0 + 8) * D_SZ + col] = v1;
    }
}

// ---------------------------------------------------------------------------
// LayerNorm over last dim (1024). One block per row, two-pass (exact).
// ---------------------------------------------------------------------------
__global__ void __launch_bounds__(256)
ln_kernel(const float* __restrict__ gamma, const float* __restrict__ beta,
          float* __restrict__ out)
{
    __shared__ float red[8];
    const int row = blockIdx.x;
    const int tid = threadIdx.x;
    const float* xr = g_q + (size_t)row * D_SZ;

    float v[4];
#pragma unroll
    for (int u = 0; u < 4; u++) v[u] = xr[tid + 256 * u];

    float s = v[0] + v[1] + v[2] + v[3];
#pragma unroll
    for (int off = 16; off > 0; off >>= 1)
        s += __shfl_xor_sync(0xffffffffu, s, off);
    if ((tid & 31) == 0) red[tid >> 5] = s;
    __syncthreads();
    float tot = 0.f;
#pragma unroll
    for (int w = 0; w < 8; w++) tot += red[w];
    const float mu = tot * (1.f / 1024.f);

    float d0 = v[0] - mu, d1 = v[1] - mu, d2 = v[2] - mu, d3 = v[3] - mu;
    float ss = d0 * d0 + d1 * d1 + d2 * d2 + d3 * d3;
#pragma unroll
    for (int off = 16; off > 0; off >>= 1)
        ss += __shfl_xor_sync(0xffffffffu, ss, off);
    __syncthreads();
    if ((tid & 31) == 0) red[tid >> 5] = ss;
    __syncthreads();
    float vtot = 0.f;
#pragma unroll
    for (int w = 0; w < 8; w++) vtot += red[w];
    const float inv = rsqrtf(vtot * (1.f / 1024.f) + 1e-5f);

#pragma unroll
    for (int u = 0; u < 4; u++) {
        const int c = tid + 256 * u;
        out[(size_t)row * D_SZ + c] = gamma[c] * (v[u] - mu) * inv + beta[c];
    }
}

// ---------------------------------------------------------------------------
extern "C" void kernel_launch(void* const* d_in, const int* in_sizes, int n_in,
                              void* d_out, int out_size)
{
    const float* Q     = (const float*)d_in[0];
    const float* K     = (const float*)d_in[1];
    const float* V     = (const float*)d_in[2];
    const int*   mask  = (const int*)  d_in[3];
    const float* Wq    = (const float*)d_in[4];
    const float* bq    = (const float*)d_in[5];
    const float* Wk    = (const float*)d_in[6];
    const float* bk    = (const float*)d_in[7];
    const float* Wv    = (const float*)d_in[8];
    const float* bv    = (const float*)d_in[9];
    const float* Wo    = (const float*)d_in[10];
    const float* bo    = (const float*)d_in[11];
    const float* gamma = (const float*)d_in[12];
    const float* beta  = (const float*)d_in[13];
    float* out = (float*)d_out;

    const dim3 gemm_grid(D_SZ / 128, M_SZ / 128);   // (8, 64)

    gemm_tf32<0><<<gemm_grid, 256>>>(Q, Wq, bq, nullptr);
    gemm_tf32<1><<<gemm_grid, 256>>>(K, Wk, bk, nullptr);
    gemm_tf32<2><<<gemm_grid, 256>>>(V, Wv, bv, nullptr);

    flash_mma<<<dim3(S_SZ / 64, H_SZ, B_SZ), 128>>>(mask);

    gemm_tf32<3><<<gemm_grid, 256>>>(nullptr, Wo, bo, Q);

    ln_kernel<<<M_SZ, 256>>>(gamma, beta, out);
}

// round 6
// speedup vs baseline: 3.1600x; 1.2290x over previous
#include <cuda_runtime.h>
#include <cstdint>
#include <cstddef>

// ---------------------------------------------------------------------------
// MultiHeadAttention fused block (round 5: conflict-free flash smem pitches,
// 128-row Q tiles / 8 warps per CTA).
// ---------------------------------------------------------------------------

#define B_SZ   4
#define S_SZ   2048
#define D_SZ   1024
#define H_SZ   16
#define DH_SZ  64
#define M_SZ   (B_SZ * S_SZ)          // 8192

#define PK 68   // Ks pitch (words): 68 % 32 == 4 -> QK B-frag conflict-free
#define PV 72   // Vs pitch (words): 72 % 32 == 8 -> PV B-frag conflict-free

__device__ float g_q[M_SZ * D_SZ];    // head-major q; later reused as pre-LN x
__device__ float g_k[M_SZ * D_SZ];    // head-major k
__device__ float g_v[M_SZ * D_SZ];    // head-major v
__device__ float g_ctx[M_SZ * D_SZ];  // merged-head ctx, row-major (B*S, D)

__device__ __forceinline__ uint32_t f2tf32(float x) {
    uint32_t r;
    asm("cvt.rna.tf32.f32 %0, %1;" : "=r"(r) : "f"(x));
    return r;
}

__device__ __forceinline__ void mma16n8k8(float c[4], const uint32_t a[4],
                                          const uint32_t b[2]) {
    asm volatile(
        "mma.sync.aligned.m16n8k8.row.col.f32.tf32.tf32.f32 "
        "{%0,%1,%2,%3}, {%4,%5,%6,%7}, {%8,%9}, {%0,%1,%2,%3};\n"
        : "+f"(c[0]), "+f"(c[1]), "+f"(c[2]), "+f"(c[3])
        : "r"(a[0]), "r"(a[1]), "r"(a[2]), "r"(a[3]), "r"(b[0]), "r"(b[1]));
}

// ---------------------------------------------------------------------------
// tf32 tensor-core GEMM (unchanged from round 3).
// ---------------------------------------------------------------------------
template <int OUTMODE>
__global__ void __launch_bounds__(256, 1)
gemm_tf32(const float* __restrict__ A, const float* __restrict__ W,
          const float* __restrict__ bias, const float* __restrict__ resid)
{
    __shared__ uint32_t As[128][36];
    __shared__ uint32_t Bs[128][36];

    const int tid  = threadIdx.x;
    const int lane = tid & 31;
    const int warp = tid >> 5;
    const int wm   = (warp & 1) * 64;
    const int wn   = (warp >> 1) * 32;
    const int g    = lane >> 2;
    const int tg   = lane & 3;

    const int m0 = blockIdx.y * 128;
    const int n0 = blockIdx.x * 128;

    const int lr = tid >> 3;
    const int lc = (tid & 7) << 2;

    const float* Asrc = (OUTMODE == 3) ? (const float*)g_ctx : A;

    float acc[4][4][4];
#pragma unroll
    for (int mi = 0; mi < 4; mi++)
#pragma unroll
        for (int ni = 0; ni < 4; ni++)
#pragma unroll
            for (int c = 0; c < 4; c++) acc[mi][ni][c] = 0.f;

    float4 av[4], bv[4];
#pragma unroll
    for (int u = 0; u < 4; u++) {
        av[u] = *(const float4*)(Asrc + (size_t)(m0 + lr + 32 * u) * D_SZ + lc);
        bv[u] = *(const float4*)(W    + (size_t)(n0 + lr + 32 * u) * D_SZ + lc);
    }

    for (int k0 = 0; k0 < D_SZ; k0 += 32) {
        __syncthreads();
#pragma unroll
        for (int u = 0; u < 4; u++) {
            uint4 pa = make_uint4(f2tf32(av[u].x), f2tf32(av[u].y),
                                  f2tf32(av[u].z), f2tf32(av[u].w));
            uint4 pb = make_uint4(f2tf32(bv[u].x), f2tf32(bv[u].y),
                                  f2tf32(bv[u].z), f2tf32(bv[u].w));
            *(uint4*)&As[lr + 32 * u][lc] = pa;
            *(uint4*)&Bs[lr + 32 * u][lc] = pb;
        }
        __syncthreads();

        if (k0 + 32 < D_SZ) {
            const int kn = k0 + 32;
#pragma unroll
            for (int u = 0; u < 4; u++) {
                av[u] = *(const float4*)(Asrc + (size_t)(m0 + lr + 32 * u) * D_SZ + kn + lc);
                bv[u] = *(const float4*)(W    + (size_t)(n0 + lr + 32 * u) * D_SZ + kn + lc);
            }
        }

#pragma unroll
        for (int kk = 0; kk < 32; kk += 8) {
            uint32_t af[4][4], bf[4][2];
#pragma unroll
            for (int mi = 0; mi < 4; mi++) {
                const int r = wm + mi * 16 + g;
                af[mi][0] = As[r    ][kk + tg];
                af[mi][1] = As[r + 8][kk + tg];
                af[mi][2] = As[r    ][kk + tg + 4];
                af[mi][3] = As[r + 8][kk + tg + 4];
            }
#pragma unroll
            for (int ni = 0; ni < 4; ni++) {
                const int c = wn + ni * 8 + g;
                bf[ni][0] = Bs[c][kk + tg];
                bf[ni][1] = Bs[c][kk + tg + 4];
            }
#pragma unroll
            for (int mi = 0; mi < 4; mi++)
#pragma unroll
                for (int ni = 0; ni < 4; ni++)
                    mma16n8k8(acc[mi][ni], af[mi], bf[ni]);
        }
    }

    if (OUTMODE < 3) {
        float* out = (OUTMODE == 0) ? g_q : (OUTMODE == 1) ? g_k : g_v;
#pragma unroll
        for (int mi = 0; mi < 4; mi++)
#pragma unroll
            for (int ni = 0; ni < 4; ni++)
#pragma unroll
                for (int h = 0; h < 2; h++) {
                    const int m = m0 + wm + mi * 16 + g + h * 8;
                    const int n = n0 + wn + ni * 8 + tg * 2;
                    const int bI = m >> 11, s = m & 2047;
                    const int head = n >> 6, dd = n & 63;
                    float2 val;
                    val.x = acc[mi][ni][h * 2 + 0] + bias[n];
                    val.y = acc[mi][ni][h * 2 + 1] + bias[n + 1];
                    *(float2*)&out[((size_t)(bI * H_SZ + head) << 17)
                                   + ((size_t)s << 6) + dd] = val;
                }
    } else {
        float* out = g_q;
#pragma unroll
        for (int mi = 0; mi < 4; mi++)
#pragma unroll
            for (int ni = 0; ni < 4; ni++)
#pragma unroll
                for (int h = 0; h < 2; h++) {
                    const int m = m0 + wm + mi * 16 + g + h * 8;
                    const int n = n0 + wn + ni * 8 + tg * 2;
                    const size_t idx = (size_t)m * D_SZ + n;
                    const float2 r2 = *(const float2*)&resid[idx];
                    float2 val;
                    val.x = acc[mi][ni][h * 2 + 0] + bias[n]     + r2.x;
                    val.y = acc[mi][ni][h * 2 + 1] + bias[n + 1] + r2.y;
                    *(float2*)&out[idx] = val;
                }
    }
}

// ---------------------------------------------------------------------------
// Flash attention, tf32 mma. 256 threads (8 warps), Q tile 128 rows, KV tile
// 64. Warp w owns q rows [16w, 16w+16). Conflict-free fragment loads:
// Ks pitch 68 (QK B-frags), Vs pitch 72 (PV B-frags). Q/P fragments stay in
// registers; online softmax on C-frag layout; C->A transpose via shfl.
// ---------------------------------------------------------------------------
__global__ void __launch_bounds__(256, 2)
flash_mma(const int* __restrict__ mask)
{
    __shared__ uint32_t Ks[64 * PK];   // 17408 B
    __shared__ uint32_t Vs[64 * PV];   // 18432 B   (total 35840 B)

    const int b    = blockIdx.z;
    const int h    = blockIdx.y;
    const int q0   = blockIdx.x * 128;
    const int tid  = threadIdx.x;
    const int lane = tid & 31;
    const int warp = tid >> 5;
    const int g    = lane >> 2;       // 0..7
    const int tg   = lane & 3;        // 0..3

    const size_t bh = (size_t)(b * H_SZ + h) * (S_SZ * DH_SZ);

    // Stage 128 Q rows through Ks (rows 0-63) and Vs (rows 64-127), raw bits.
    {
        const float4* gq = (const float4*)(g_q + bh + (size_t)q0 * DH_SZ);
        for (int idx = tid; idx < 2048; idx += 256) {
            float4 v = gq[idx];
            const int r = idx >> 4, c = (idx & 15) << 2;
            uint32_t* dst = (r < 64) ? &Ks[r * PK + c] : &Vs[(r - 64) * PV + c];
            dst[0] = __float_as_uint(v.x);
            dst[1] = __float_as_uint(v.y);
            dst[2] = __float_as_uint(v.z);
            dst[3] = __float_as_uint(v.w);
        }
    }
    __syncthreads();

    // Extract Q fragments (pre-scaled by 1/8), warps 0-3 from Ks, 4-7 from Vs.
    uint32_t qf[8][4];
    {
        const int r = warp * 16 + g;
        const uint32_t* b0 = (r < 64) ? &Ks[r * PK] : &Vs[(r - 64) * PV];
        const uint32_t* b1 = (r + 8 < 64) ? &Ks[(r + 8) * PK] : &Vs[(r + 8 - 64) * PV];
#pragma unroll
        for (int k8 = 0; k8 < 8; k8++) {
            const int k = k8 * 8;
            qf[k8][0] = f2tf32(0.125f * __uint_as_float(b0[k + tg]));
            qf[k8][1] = f2tf32(0.125f * __uint_as_float(b1[k + tg]));
            qf[k8][2] = f2tf32(0.125f * __uint_as_float(b0[k + tg + 4]));
            qf[k8][3] = f2tf32(0.125f * __uint_as_float(b1[k + tg + 4]));
        }
    }

    float of[8][4];
#pragma unroll
    for (int ni = 0; ni < 8; ni++)
#pragma unroll
        for (int c = 0; c < 4; c++) of[ni][c] = 0.f;
    float m0 = -1e30f, m1 = -1e30f, l0 = 0.f, l1 = 0.f;

    const int* mrow = mask + b * S_SZ;

    for (int t = 0; t < S_SZ / 64; t++) {
        __syncthreads();   // prior tile's frag reads (and Q extract) done
        {
            const float4* gk = (const float4*)(g_k + bh + (size_t)(t * 64) * DH_SZ);
            const float4* gv = (const float4*)(g_v + bh + (size_t)(t * 64) * DH_SZ);
            for (int idx = tid; idx < 1024; idx += 256) {
                const int r = idx >> 4, c = (idx & 15) << 2;
                float4 kv = gk[idx];
                float4 vv = gv[idx];
                uint32_t* kd = &Ks[r * PK + c];
                uint32_t* vd = &Vs[r * PV + c];
                kd[0] = f2tf32(kv.x); kd[1] = f2tf32(kv.y);
                kd[2] = f2tf32(kv.z); kd[3] = f2tf32(kv.w);
                vd[0] = f2tf32(vv.x); vd[1] = f2tf32(vv.y);
                vd[2] = f2tf32(vv.z); vd[3] = f2tf32(vv.w);
            }
        }
        __syncthreads();

        // S = (Q/8) K^T  -- 8 n-tiles of m16n8, contraction over dh=64
        float s_[8][4];
#pragma unroll
        for (int nt = 0; nt < 8; nt++) {
            s_[nt][0] = 0.f; s_[nt][1] = 0.f; s_[nt][2] = 0.f; s_[nt][3] = 0.f;
#pragma unroll
            for (int k8 = 0; k8 < 8; k8++) {
                uint32_t bf[2];
                bf[0] = Ks[(nt * 8 + g) * PK + k8 * 8 + tg];
                bf[1] = Ks[(nt * 8 + g) * PK + k8 * 8 + tg + 4];
                mma16n8k8(s_[nt], qf[k8], bf);
            }
        }

        // mask (additive)
#pragma unroll
        for (int nt = 0; nt < 8; nt++) {
            const int mc = t * 64 + nt * 8 + tg * 2;
            const float ma = (mrow[mc]     == 0) ? -1e9f : 0.f;
            const float mb = (mrow[mc + 1] == 0) ? -1e9f : 0.f;
            s_[nt][0] += ma; s_[nt][1] += mb;
            s_[nt][2] += ma; s_[nt][3] += mb;
        }

        // online softmax: rows g (c0,c1) and g+8 (c2,c3), quad-lane reduce
        float rm0 = -1e30f, rm1 = -1e30f;
#pragma unroll
        for (int nt = 0; nt < 8; nt++) {
            rm0 = fmaxf(rm0, fmaxf(s_[nt][0], s_[nt][1]));
            rm1 = fmaxf(rm1, fmaxf(s_[nt][2], s_[nt][3]));
        }
        rm0 = fmaxf(rm0, __shfl_xor_sync(0xffffffffu, rm0, 1));
        rm0 = fmaxf(rm0, __shfl_xor_sync(0xffffffffu, rm0, 2));
        rm1 = fmaxf(rm1, __shfl_xor_sync(0xffffffffu, rm1, 1));
        rm1 = fmaxf(rm1, __shfl_xor_sync(0xffffffffu, rm1, 2));

        const float mn0 = fmaxf(m0, rm0);
        const float mn1 = fmaxf(m1, rm1);
        const float al0 = __expf(m0 - mn0);
        const float al1 = __expf(m1 - mn1);
        m0 = mn0; m1 = mn1;

        float rs0 = 0.f, rs1 = 0.f;
#pragma unroll
        for (int nt = 0; nt < 8; nt++) {
            s_[nt][0] = __expf(s_[nt][0] - mn0);
            s_[nt][1] = __expf(s_[nt][1] - mn0);
            s_[nt][2] = __expf(s_[nt][2] - mn1);
            s_[nt][3] = __expf(s_[nt][3] - mn1);
            rs0 += s_[nt][0] + s_[nt][1];
            rs1 += s_[nt][2] + s_[nt][3];
        }
        rs0 += __shfl_xor_sync(0xffffffffu, rs0, 1);
        rs0 += __shfl_xor_sync(0xffffffffu, rs0, 2);
        rs1 += __shfl_xor_sync(0xffffffffu, rs1, 1);
        rs1 += __shfl_xor_sync(0xffffffffu, rs1, 2);
        l0 = l0 * al0 + rs0;
        l1 = l1 * al1 + rs1;

#pragma unroll
        for (int ni = 0; ni < 8; ni++) {
            of[ni][0] *= al0; of[ni][1] *= al0;
            of[ni][2] *= al1; of[ni][3] *= al1;
        }

        // O += P V : per kv-block j, transpose C-frag -> A-frag via shuffles
        const int srcA = (lane & ~3) | (tg >> 1);
        const int srcB = srcA + 2;
        const bool odd = (tg & 1);
#pragma unroll
        for (int j = 0; j < 8; j++) {
            const float x0 = __shfl_sync(0xffffffffu, s_[j][0], srcA);
            const float x1 = __shfl_sync(0xffffffffu, s_[j][1], srcA);
            const float y0 = __shfl_sync(0xffffffffu, s_[j][2], srcA);
            const float y1 = __shfl_sync(0xffffffffu, s_[j][3], srcA);
            const float x2 = __shfl_sync(0xffffffffu, s_[j][0], srcB);
            const float x3 = __shfl_sync(0xffffffffu, s_[j][1], srcB);
            const float y2 = __shfl_sync(0xffffffffu, s_[j][2], srcB);
            const float y3 = __shfl_sync(0xffffffffu, s_[j][3], srcB);
            uint32_t pa[4];
            pa[0] = f2tf32(odd ? x1 : x0);
            pa[1] = f2tf32(odd ? y1 : y0);
            pa[2] = f2tf32(odd ? x3 : x2);
            pa[3] = f2tf32(odd ? y3 : y2);
#pragma unroll
            for (int ni = 0; ni < 8; ni++) {
                uint32_t bf[2];
                bf[0] = Vs[(j * 8 + tg) * PV + ni * 8 + g];
                bf[1] = Vs[(j * 8 + tg + 4) * PV + ni * 8 + g];
                mma16n8k8(of[ni], pa, bf);
            }
        }
    }

    // epilogue: ctx in merged-head row-major (B*S, D)
    const float il0 = 1.f / l0;
    const float il1 = 1.f / l1;
    const int row0 = b * S_SZ + q0 + warp * 16 + g;
    const int colb = h * DH_SZ;
#pragma unroll
    for (int ni = 0; ni < 8; ni++) {
        const int col = colb + ni * 8 + tg * 2;
        float2 v0, v1;
        v0.x = of[ni][0] * il0; v0.y = of[ni][1] * il0;
        v1.x = of[ni][2] * il1; v1.y = of[ni][3] * il1;
        *(float2*)&g_ctx[(size_t)row0 * D_SZ + col]       = v0;
        *(float2*)&g_ctx[(size_t)(row0 + 8) * D_SZ + col] = v1;
    }
}

// ---------------------------------------------------------------------------
// LayerNorm over last dim (1024). One block per row, two-pass (exact).
// ---------------------------------------------------------------------------
__global__ void __launch_bounds__(256)
ln_kernel(const float* __restrict__ gamma, const float* __restrict__ beta,
          float* __restrict__ out)
{
    __shared__ float red[8];
    const int row = blockIdx.x;
    const int tid = threadIdx.x;
    const float* xr = g_q + (size_t)row * D_SZ;

    float v[4];
#pragma unroll
    for (int u = 0; u < 4; u++) v[u] = xr[tid + 256 * u];

    float s = v[0] + v[1] + v[2] + v[3];
#pragma unroll
    for (int off = 16; off > 0; off >>= 1)
        s += __shfl_xor_sync(0xffffffffu, s, off);
    if ((tid & 31) == 0) red[tid >> 5] = s;
    __syncthreads();
    float tot = 0.f;
#pragma unroll
    for (int w = 0; w < 8; w++) tot += red[w];
    const float mu = tot * (1.f / 1024.f);

    float d0 = v[0] - mu, d1 = v[1] - mu, d2 = v[2] - mu, d3 = v[3] - mu;
    float ss = d0 * d0 + d1 * d1 + d2 * d2 + d3 * d3;
#pragma unroll
    for (int off = 16; off > 0; off >>= 1)
        ss += __shfl_xor_sync(0xffffffffu, ss, off);
    __syncthreads();
    if ((tid & 31) == 0) red[tid >> 5] = ss;
    __syncthreads();
    float vtot = 0.f;
#pragma unroll
    for (int w = 0; w < 8; w++) vtot += red[w];
    const float inv = rsqrtf(vtot * (1.f / 1024.f) + 1e-5f);

#pragma unroll
    for (int u = 0; u < 4; u++) {
        const int c = tid + 256 * u;
        out[(size_t)row * D_SZ + c] = gamma[c] * (v[u] - mu) * inv + beta[c];
    }
}

// ---------------------------------------------------------------------------
extern "C" void kernel_launch(void* const* d_in, const int* in_sizes, int n_in,
                              void* d_out, int out_size)
{
    const float* Q     = (const float*)d_in[0];
    const float* K     = (const float*)d_in[1];
    const float* V     = (const float*)d_in[2];
    const int*   mask  = (const int*)  d_in[3];
    const float* Wq    = (const float*)d_in[4];
    const float* bq    = (const float*)d_in[5];
    const float* Wk    = (const float*)d_in[6];
    const float* bk    = (const float*)d_in[7];
    const float* Wv    = (const float*)d_in[8];
    const float* bv    = (const float*)d_in[9];
    const float* Wo    = (const float*)d_in[10];
    const float* bo    = (const float*)d_in[11];
    const float* gamma = (const float*)d_in[12];
    const float* beta  = (const float*)d_in[13];
    float* out = (float*)d_out;

    const dim3 gemm_grid(D_SZ / 128, M_SZ / 128);   // (8, 64)

    gemm_tf32<0><<<gemm_grid, 256>>>(Q, Wq, bq, nullptr);
    gemm_tf32<1><<<gemm_grid, 256>>>(K, Wk, bk, nullptr);
    gemm_tf32<2><<<gemm_grid, 256>>>(V, Wv, bv, nullptr);

    flash_mma<<<dim3(S_SZ / 128, H_SZ, B_SZ), 256>>>(mask);

    gemm_tf32<3><<<gemm_grid, 256>>>(nullptr, Wo, bo, Q);

    ln_kernel<<<M_SZ, 256>>>(gamma, beta, out);
}

// round 7
// speedup vs baseline: 3.7068x; 1.1730x over previous
#include <cuda_runtime.h>
#include <cstdint>
#include <cstddef>

// ---------------------------------------------------------------------------
// MultiHeadAttention fused block (round 6: cp.async double-buffered flash,
// raw-fp32-as-tf32 operands).
// ---------------------------------------------------------------------------

#define B_SZ   4
#define S_SZ   2048
#define D_SZ   1024
#define H_SZ   16
#define DH_SZ  64
#define M_SZ   (B_SZ * S_SZ)          // 8192

#define PK 68   // Ks pitch (words): 68 % 32 == 4 -> QK B-frag conflict-free
#define PV 72   // Vs pitch (words): 72 % 32 == 8 -> PV B-frag conflict-free
#define STAGE_W (64 * PK + 64 * PV)   // 8960 words per stage
#define FLASH_SMEM_B (2 * STAGE_W * 4) // 71680 bytes

__device__ float g_q[M_SZ * D_SZ];    // head-major q; later reused as pre-LN x
__device__ float g_k[M_SZ * D_SZ];    // head-major k
__device__ float g_v[M_SZ * D_SZ];    // head-major v
__device__ float g_ctx[M_SZ * D_SZ];  // merged-head ctx, row-major (B*S, D)

__device__ __forceinline__ uint32_t f2tf32(float x) {
    uint32_t r;
    asm("cvt.rna.tf32.f32 %0, %1;" : "=r"(r) : "f"(x));
    return r;
}

__device__ __forceinline__ void mma16n8k8(float c[4], const uint32_t a[4],
                                          const uint32_t b[2]) {
    asm volatile(
        "mma.sync.aligned.m16n8k8.row.col.f32.tf32.tf32.f32 "
        "{%0,%1,%2,%3}, {%4,%5,%6,%7}, {%8,%9}, {%0,%1,%2,%3};\n"
        : "+f"(c[0]), "+f"(c[1]), "+f"(c[2]), "+f"(c[3])
        : "r"(a[0]), "r"(a[1]), "r"(a[2]), "r"(a[3]), "r"(b[0]), "r"(b[1]));
}

__device__ __forceinline__ void cp16(uint32_t smem_dst, const void* gmem_src) {
    asm volatile("cp.async.cg.shared.global [%0], [%1], 16;\n"
                 :: "r"(smem_dst), "l"(gmem_src));
}

// ---------------------------------------------------------------------------
// tf32 tensor-core GEMM (unchanged from round 3).
// ---------------------------------------------------------------------------
template <int OUTMODE>
__global__ void __launch_bounds__(256, 1)
gemm_tf32(const float* __restrict__ A, const float* __restrict__ W,
          const float* __restrict__ bias, const float* __restrict__ resid)
{
    __shared__ uint32_t As[128][36];
    __shared__ uint32_t Bs[128][36];

    const int tid  = threadIdx.x;
    const int lane = tid & 31;
    const int warp = tid >> 5;
    const int wm   = (warp & 1) * 64;
    const int wn   = (warp >> 1) * 32;
    const int g    = lane >> 2;
    const int tg   = lane & 3;

    const int m0 = blockIdx.y * 128;
    const int n0 = blockIdx.x * 128;

    const int lr = tid >> 3;
    const int lc = (tid & 7) << 2;

    const float* Asrc = (OUTMODE == 3) ? (const float*)g_ctx : A;

    float acc[4][4][4];
#pragma unroll
    for (int mi = 0; mi < 4; mi++)
#pragma unroll
        for (int ni = 0; ni < 4; ni++)
#pragma unroll
            for (int c = 0; c < 4; c++) acc[mi][ni][c] = 0.f;

    float4 av[4], bv[4];
#pragma unroll
    for (int u = 0; u < 4; u++) {
        av[u] = *(const float4*)(Asrc + (size_t)(m0 + lr + 32 * u) * D_SZ + lc);
        bv[u] = *(const float4*)(W    + (size_t)(n0 + lr + 32 * u) * D_SZ + lc);
    }

    for (int k0 = 0; k0 < D_SZ; k0 += 32) {
        __syncthreads();
#pragma unroll
        for (int u = 0; u < 4; u++) {
            uint4 pa = make_uint4(f2tf32(av[u].x), f2tf32(av[u].y),
                                  f2tf32(av[u].z), f2tf32(av[u].w));
            uint4 pb = make_uint4(f2tf32(bv[u].x), f2tf32(bv[u].y),
                                  f2tf32(bv[u].z), f2tf32(bv[u].w));
            *(uint4*)&As[lr + 32 * u][lc] = pa;
            *(uint4*)&Bs[lr + 32 * u][lc] = pb;
        }
        __syncthreads();

        if (k0 + 32 < D_SZ) {
            const int kn = k0 + 32;
#pragma unroll
            for (int u = 0; u < 4; u++) {
                av[u] = *(const float4*)(Asrc + (size_t)(m0 + lr + 32 * u) * D_SZ + kn + lc);
                bv[u] = *(const float4*)(W    + (size_t)(n0 + lr + 32 * u) * D_SZ + kn + lc);
            }
        }

#pragma unroll
        for (int kk = 0; kk < 32; kk += 8) {
            uint32_t af[4][4], bf[4][2];
#pragma unroll
            for (int mi = 0; mi < 4; mi++) {
                const int r = wm + mi * 16 + g;
                af[mi][0] = As[r    ][kk + tg];
                af[mi][1] = As[r + 8][kk + tg];
                af[mi][2] = As[r    ][kk + tg + 4];
                af[mi][3] = As[r + 8][kk + tg + 4];
            }
#pragma unroll
            for (int ni = 0; ni < 4; ni++) {
                const int c = wn + ni * 8 + g;
                bf[ni][0] = Bs[c][kk + tg];
                bf[ni][1] = Bs[c][kk + tg + 4];
            }
#pragma unroll
            for (int mi = 0; mi < 4; mi++)
#pragma unroll
                for (int ni = 0; ni < 4; ni++)
                    mma16n8k8(acc[mi][ni], af[mi], bf[ni]);
        }
    }

    if (OUTMODE < 3) {
        float* out = (OUTMODE == 0) ? g_q : (OUTMODE == 1) ? g_k : g_v;
#pragma unroll
        for (int mi = 0; mi < 4; mi++)
#pragma unroll
            for (int ni = 0; ni < 4; ni++)
#pragma unroll
                for (int h = 0; h < 2; h++) {
                    const int m = m0 + wm + mi * 16 + g + h * 8;
                    const int n = n0 + wn + ni * 8 + tg * 2;
                    const int bI = m >> 11, s = m & 2047;
                    const int head = n >> 6, dd = n & 63;
                    float2 val;
                    val.x = acc[mi][ni][h * 2 + 0] + bias[n];
                    val.y = acc[mi][ni][h * 2 + 1] + bias[n + 1];
                    *(float2*)&out[((size_t)(bI * H_SZ + head) << 17)
                                   + ((size_t)s << 6) + dd] = val;
                }
    } else {
        float* out = g_q;
#pragma unroll
        for (int mi = 0; mi < 4; mi++)
#pragma unroll
            for (int ni = 0; ni < 4; ni++)
#pragma unroll
                for (int h = 0; h < 2; h++) {
                    const int m = m0 + wm + mi * 16 + g + h * 8;
                    const int n = n0 + wn + ni * 8 + tg * 2;
                    const size_t idx = (size_t)m * D_SZ + n;
                    const float2 r2 = *(const float2*)&resid[idx];
                    float2 val;
                    val.x = acc[mi][ni][h * 2 + 0] + bias[n]     + r2.x;
                    val.y = acc[mi][ni][h * 2 + 1] + bias[n + 1] + r2.y;
                    *(float2*)&out[idx] = val;
                }
    }
}

// ---------------------------------------------------------------------------
// Flash attention, tf32 mma, cp.async double-buffered KV staging.
// 256 threads (8 warps), Q tile 128 rows, KV tile 64. Raw fp32 bits are fed
// to tf32 mma for K/V/P (hardware truncation); only Q frags use rna convert.
// ---------------------------------------------------------------------------
__global__ void __launch_bounds__(256, 2)
flash_mma(const int* __restrict__ mask)
{
    extern __shared__ uint32_t smbuf[];   // 2 stages x (Ks 64xPK | Vs 64xPV)

    const int b    = blockIdx.z;
    const int h    = blockIdx.y;
    const int q0   = blockIdx.x * 128;
    const int tid  = threadIdx.x;
    const int lane = tid & 31;
    const int warp = tid >> 5;
    const int g    = lane >> 2;       // 0..7
    const int tg   = lane & 3;        // 0..3

    const size_t bh = (size_t)(b * H_SZ + h) * (S_SZ * DH_SZ);
    const uint32_t sbase = (uint32_t)__cvta_generic_to_shared(smbuf);

    // ---- Stage 128 Q rows into stage 0 (raw bits), extract fragments ----
    {
        const float4* gq = (const float4*)(g_q + bh + (size_t)q0 * DH_SZ);
        for (int idx = tid; idx < 2048; idx += 256) {
            const int r = idx >> 4, c = (idx & 15) << 2;
            const uint32_t off = (r < 64) ? (r * PK + c)
                                          : (64 * PK + (r - 64) * PV + c);
            cp16(sbase + off * 4, gq + idx);
        }
        asm volatile("cp.async.commit_group;\n");
        asm volatile("cp.async.wait_group 0;\n");
        __syncthreads();
    }

    uint32_t qf[8][4];
    {
        const int r = warp * 16 + g;
        const uint32_t* b0 = (r < 64) ? &smbuf[r * PK]
                                      : &smbuf[64 * PK + (r - 64) * PV];
        const int r1 = r + 8;
        const uint32_t* b1 = (r1 < 64) ? &smbuf[r1 * PK]
                                       : &smbuf[64 * PK + (r1 - 64) * PV];
#pragma unroll
        for (int k8 = 0; k8 < 8; k8++) {
            const int k = k8 * 8;
            qf[k8][0] = f2tf32(0.125f * __uint_as_float(b0[k + tg]));
            qf[k8][1] = f2tf32(0.125f * __uint_as_float(b1[k + tg]));
            qf[k8][2] = f2tf32(0.125f * __uint_as_float(b0[k + tg + 4]));
            qf[k8][3] = f2tf32(0.125f * __uint_as_float(b1[k + tg + 4]));
        }
    }
    __syncthreads();   // Q reads done; stage 0 may be overwritten

    // ---- KV pipeline ----
    const float4* gkb = (const float4*)(g_k + bh);
    const float4* gvb = (const float4*)(g_v + bh);
    // tile t occupies rows [t*64, t*64+64): float4 index base t*1024

    auto issue_tile = [&](int t, int stage) {
        const uint32_t kb = sbase + (stage * STAGE_W) * 4;
        const uint32_t vb = kb + (64 * PK) * 4;
        const float4* gk = gkb + (size_t)t * 1024;
        const float4* gv = gvb + (size_t)t * 1024;
#pragma unroll
        for (int u = 0; u < 4; u++) {
            const int idx = tid + 256 * u;
            const int r = idx >> 4, c = (idx & 15) << 2;
            cp16(kb + (r * PK + c) * 4, gk + idx);
            cp16(vb + (r * PV + c) * 4, gv + idx);
        }
        asm volatile("cp.async.commit_group;\n");
    };

    issue_tile(0, 0);
    issue_tile(1, 1);

    float of[8][4];
#pragma unroll
    for (int ni = 0; ni < 8; ni++)
#pragma unroll
        for (int c = 0; c < 4; c++) of[ni][c] = 0.f;
    float m0 = -1e30f, m1 = -1e30f, l0 = 0.f, l1 = 0.f;

    const int* mrow = mask + b * S_SZ;
    const int NT = S_SZ / 64;   // 32

    for (int t = 0; t < NT; t++) {
        if (t + 1 < NT) asm volatile("cp.async.wait_group 1;\n");
        else            asm volatile("cp.async.wait_group 0;\n");
        __syncthreads();

        const uint32_t* KsS = &smbuf[(t & 1) * STAGE_W];
        const uint32_t* VsS = KsS + 64 * PK;

        // S = (Q/8) K^T  -- 8 n-tiles of m16n8, contraction over dh=64
        float s_[8][4];
#pragma unroll
        for (int nt = 0; nt < 8; nt++) {
            s_[nt][0] = 0.f; s_[nt][1] = 0.f; s_[nt][2] = 0.f; s_[nt][3] = 0.f;
#pragma unroll
            for (int k8 = 0; k8 < 8; k8++) {
                uint32_t bf[2];
                bf[0] = KsS[(nt * 8 + g) * PK + k8 * 8 + tg];
                bf[1] = KsS[(nt * 8 + g) * PK + k8 * 8 + tg + 4];
                mma16n8k8(s_[nt], qf[k8], bf);
            }
        }

        // mask (additive)
#pragma unroll
        for (int nt = 0; nt < 8; nt++) {
            const int mc = t * 64 + nt * 8 + tg * 2;
            const float ma = (mrow[mc]     == 0) ? -1e9f : 0.f;
            const float mb = (mrow[mc + 1] == 0) ? -1e9f : 0.f;
            s_[nt][0] += ma; s_[nt][1] += mb;
            s_[nt][2] += ma; s_[nt][3] += mb;
        }

        // online softmax: rows g (c0,c1) and g+8 (c2,c3), quad-lane reduce
        float rm0 = -1e30f, rm1 = -1e30f;
#pragma unroll
        for (int nt = 0; nt < 8; nt++) {
            rm0 = fmaxf(rm0, fmaxf(s_[nt][0], s_[nt][1]));
            rm1 = fmaxf(rm1, fmaxf(s_[nt][2], s_[nt][3]));
        }
        rm0 = fmaxf(rm0, __shfl_xor_sync(0xffffffffu, rm0, 1));
        rm0 = fmaxf(rm0, __shfl_xor_sync(0xffffffffu, rm0, 2));
        rm1 = fmaxf(rm1, __shfl_xor_sync(0xffffffffu, rm1, 1));
        rm1 = fmaxf(rm1, __shfl_xor_sync(0xffffffffu, rm1, 2));

        const float mn0 = fmaxf(m0, rm0);
        const float mn1 = fmaxf(m1, rm1);
        const float al0 = __expf(m0 - mn0);
        const float al1 = __expf(m1 - mn1);
        m0 = mn0; m1 = mn1;

        float rs0 = 0.f, rs1 = 0.f;
#pragma unroll
        for (int nt = 0; nt < 8; nt++) {
            s_[nt][0] = __expf(s_[nt][0] - mn0);
            s_[nt][1] = __expf(s_[nt][1] - mn0);
            s_[nt][2] = __expf(s_[nt][2] - mn1);
            s_[nt][3] = __expf(s_[nt][3] - mn1);
            rs0 += s_[nt][0] + s_[nt][1];
            rs1 += s_[nt][2] + s_[nt][3];
        }
        rs0 += __shfl_xor_sync(0xffffffffu, rs0, 1);
        rs0 += __shfl_xor_sync(0xffffffffu, rs0, 2);
        rs1 += __shfl_xor_sync(0xffffffffu, rs1, 1);
        rs1 += __shfl_xor_sync(0xffffffffu, rs1, 2);
        l0 = l0 * al0 + rs0;
        l1 = l1 * al1 + rs1;

#pragma unroll
        for (int ni = 0; ni < 8; ni++) {
            of[ni][0] *= al0; of[ni][1] *= al0;
            of[ni][2] *= al1; of[ni][3] *= al1;
        }

        // O += P V : per kv-block j, transpose C-frag -> A-frag via shuffles
        const int srcA = (lane & ~3) | (tg >> 1);
        const int srcB = srcA + 2;
        const bool odd = (tg & 1);
#pragma unroll
        for (int j = 0; j < 8; j++) {
            const float x0 = __shfl_sync(0xffffffffu, s_[j][0], srcA);
            const float x1 = __shfl_sync(0xffffffffu, s_[j][1], srcA);
            const float y0 = __shfl_sync(0xffffffffu, s_[j][2], srcA);
            const float y1 = __shfl_sync(0xffffffffu, s_[j][3], srcA);
            const float x2 = __shfl_sync(0xffffffffu, s_[j][0], srcB);
            const float x3 = __shfl_sync(0xffffffffu, s_[j][1], srcB);
            const float y2 = __shfl_sync(0xffffffffu, s_[j][2], srcB);
            const float y3 = __shfl_sync(0xffffffffu, s_[j][3], srcB);
            uint32_t pa[4];
            pa[0] = __float_as_uint(odd ? x1 : x0);
            pa[1] = __float_as_uint(odd ? y1 : y0);
            pa[2] = __float_as_uint(odd ? x3 : x2);
            pa[3] = __float_as_uint(odd ? y3 : y2);
#pragma unroll
            for (int ni = 0; ni < 8; ni++) {
                uint32_t bf[2];
                bf[0] = VsS[(j * 8 + tg) * PV + ni * 8 + g];
                bf[1] = VsS[(j * 8 + tg + 4) * PV + ni * 8 + g];
                mma16n8k8(of[ni], pa, bf);
            }
        }

        __syncthreads();   // all warps done with this stage
        if (t + 2 < NT) issue_tile(t + 2, t & 1);
    }

    // epilogue: ctx in merged-head row-major (B*S, D)
    const float il0 = 1.f / l0;
    const float il1 = 1.f / l1;
    const int row0 = b * S_SZ + q0 + warp * 16 + g;
    const int colb = h * DH_SZ;
#pragma unroll
    for (int ni = 0; ni < 8; ni++) {
        const int col = colb + ni * 8 + tg * 2;
        float2 v0, v1;
        v0.x = of[ni][0] * il0; v0.y = of[ni][1] * il0;
        v1.x = of[ni][2] * il1; v1.y = of[ni][3] * il1;
        *(float2*)&g_ctx[(size_t)row0 * D_SZ + col]       = v0;
        *(float2*)&g_ctx[(size_t)(row0 + 8) * D_SZ + col] = v1;
    }
}

// ---------------------------------------------------------------------------
// LayerNorm over last dim (1024). One block per row, two-pass (exact).
// ---------------------------------------------------------------------------
__global__ void __launch_bounds__(256)
ln_kernel(const float* __restrict__ gamma, const float* __restrict__ beta,
          float* __restrict__ out)
{
    __shared__ float red[8];
    const int row = blockIdx.x;
    const int tid = threadIdx.x;
    const float* xr = g_q + (size_t)row * D_SZ;

    float v[4];
#pragma unroll
    for (int u = 0; u < 4; u++) v[u] = xr[tid + 256 * u];

    float s = v[0] + v[1] + v[2] + v[3];
#pragma unroll
    for (int off = 16; off > 0; off >>= 1)
        s += __shfl_xor_sync(0xffffffffu, s, off);
    if ((tid & 31) == 0) red[tid >> 5] = s;
    __syncthreads();
    float tot = 0.f;
#pragma unroll
    for (int w = 0; w < 8; w++) tot += red[w];
    const float mu = tot * (1.f / 1024.f);

    float d0 = v[0] - mu, d1 = v[1] - mu, d2 = v[2] - mu, d3 = v[3] - mu;
    float ss = d0 * d0 + d1 * d1 + d2 * d2 + d3 * d3;
#pragma unroll
    for (int off = 16; off > 0; off >>= 1)
        ss += __shfl_xor_sync(0xffffffffu, ss, off);
    __syncthreads();
    if ((tid & 31) == 0) red[tid >> 5] = ss;
    __syncthreads();
    float vtot = 0.f;
#pragma unroll
    for (int w = 0; w < 8; w++) vtot += red[w];
    const float inv = rsqrtf(vtot * (1.f / 1024.f) + 1e-5f);

#pragma unroll
    for (int u = 0; u < 4; u++) {
        const int c = tid + 256 * u;
        out[(size_t)row * D_SZ + c] = gamma[c] * (v[u] - mu) * inv + beta[c];
    }
}

// ---------------------------------------------------------------------------
extern "C" void kernel_launch(void* const* d_in, const int* in_sizes, int n_in,
                              void* d_out, int out_size)
{
    const float* Q     = (const float*)d_in[0];
    const float* K     = (const float*)d_in[1];
    const float* V     = (const float*)d_in[2];
    const int*   mask  = (const int*)  d_in[3];
    const float* Wq    = (const float*)d_in[4];
    const float* bq    = (const float*)d_in[5];
    const float* Wk    = (const float*)d_in[6];
    const float* bk    = (const float*)d_in[7];
    const float* Wv    = (const float*)d_in[8];
    const float* bv    = (const float*)d_in[9];
    const float* Wo    = (const float*)d_in[10];
    const float* bo    = (const float*)d_in[11];
    const float* gamma = (const float*)d_in[12];
    const float* beta  = (const float*)d_in[13];
    float* out = (float*)d_out;

    // Capture-safe (not a stream op); clear any sticky benign error.
    cudaFuncSetAttribute(flash_mma,
                         cudaFuncAttributeMaxDynamicSharedMemorySize,
                         FLASH_SMEM_B);
    (void)cudaGetLastError();

    const dim3 gemm_grid(D_SZ / 128, M_SZ / 128);   // (8, 64)

    gemm_tf32<0><<<gemm_grid, 256>>>(Q, Wq, bq, nullptr);
    gemm_tf32<1><<<gemm_grid, 256>>>(K, Wk, bk, nullptr);
    gemm_tf32<2><<<gemm_grid, 256>>>(V, Wv, bv, nullptr);

    flash_mma<<<dim3(S_SZ / 128, H_SZ, B_SZ), 256, FLASH_SMEM_B>>>(mask);

    gemm_tf32<3><<<gemm_grid, 256>>>(nullptr, Wo, bo, Q);

    ln_kernel<<<M_SZ, 256>>>(gamma, beta, out);
}

// round 8
// speedup vs baseline: 4.1960x; 1.1320x over previous
#include <cuda_runtime.h>
#include <cstdint>
#include <cstddef>

// ---------------------------------------------------------------------------
// MultiHeadAttention fused block (round 7: cp.async double-buffered GEMMs,
// fused QKV launch, raw-fp32-as-tf32 everywhere).
// ---------------------------------------------------------------------------

#define B_SZ   4
#define S_SZ   2048
#define D_SZ   1024
#define H_SZ   16
#define DH_SZ  64
#define M_SZ   (B_SZ * S_SZ)          // 8192

#define PK 68   // flash Ks pitch: 68 % 32 == 4 -> QK B-frag conflict-free
#define PV 72   // flash Vs pitch: 72 % 32 == 8 -> PV B-frag conflict-free
#define STAGE_W (64 * PK + 64 * PV)   // flash stage words
#define FLASH_SMEM_B (2 * STAGE_W * 4)

#define GP 36                          // gemm smem pitch (words)
#define GSTAGE (128 * GP * 2)          // words per gemm stage (A+B) = 9216
#define GEMM_SMEM_B (2 * GSTAGE * 4)   // 73728 bytes

__device__ float g_q[M_SZ * D_SZ];    // head-major q; later reused as pre-LN x
__device__ float g_k[M_SZ * D_SZ];    // head-major k
__device__ float g_v[M_SZ * D_SZ];    // head-major v
__device__ float g_ctx[M_SZ * D_SZ];  // merged-head ctx, row-major (B*S, D)

__device__ __forceinline__ uint32_t f2tf32(float x) {
    uint32_t r;
    asm("cvt.rna.tf32.f32 %0, %1;" : "=r"(r) : "f"(x));
    return r;
}

__device__ __forceinline__ void mma16n8k8(float c[4], const uint32_t a[4],
                                          const uint32_t b[2]) {
    asm volatile(
        "mma.sync.aligned.m16n8k8.row.col.f32.tf32.tf32.f32 "
        "{%0,%1,%2,%3}, {%4,%5,%6,%7}, {%8,%9}, {%0,%1,%2,%3};\n"
        : "+f"(c[0]), "+f"(c[1]), "+f"(c[2]), "+f"(c[3])
        : "r"(a[0]), "r"(a[1]), "r"(a[2]), "r"(a[3]), "r"(b[0]), "r"(b[1]));
}

__device__ __forceinline__ void cp16(uint32_t smem_dst, const void* gmem_src) {
    asm volatile("cp.async.cg.shared.global [%0], [%1], 16;\n"
                 :: "r"(smem_dst), "l"(gmem_src));
}

// ---------------------------------------------------------------------------
// Pipelined tf32 GEMM mainloop (shared by QKV and O kernels).
// Computes acc[4][4][4] for a 128x128 tile of A @ W^T, BK=32, double-buffered
// cp.async staging, raw fp32 bits as tf32 operands.
// ---------------------------------------------------------------------------
__device__ __forceinline__ void gemm_mainloop(
    const float* __restrict__ A, const float* __restrict__ W,
    int m0, int n0, uint32_t* smbuf, uint32_t sbase, float acc[4][4][4])
{
    const int tid  = threadIdx.x;
    const int lane = tid & 31;
    const int warp = tid >> 5;
    const int wm   = (warp & 1) * 64;
    const int wn   = (warp >> 1) * 32;
    const int g    = lane >> 2;
    const int tg   = lane & 3;
    const int lr   = tid >> 3;          // 0..31
    const int lc   = (tid & 7) << 2;    // 0,4,...,28

#pragma unroll
    for (int mi = 0; mi < 4; mi++)
#pragma unroll
        for (int ni = 0; ni < 4; ni++)
#pragma unroll
            for (int c = 0; c < 4; c++) acc[mi][ni][c] = 0.f;

    auto issue = [&](int k0, int stage) {
        const uint32_t ab = sbase + (stage * GSTAGE) * 4;
        const uint32_t bb = ab + (128 * GP) * 4;
#pragma unroll
        for (int u = 0; u < 4; u++) {
            const int row = lr + 32 * u;
            cp16(ab + (row * GP + lc) * 4, A + (size_t)(m0 + row) * D_SZ + k0 + lc);
            cp16(bb + (row * GP + lc) * 4, W + (size_t)(n0 + row) * D_SZ + k0 + lc);
        }
        asm volatile("cp.async.commit_group;\n");
    };

    issue(0, 0);
    issue(32, 1);

    const int NK = D_SZ / 32;   // 32
    for (int kt = 0; kt < NK; kt++) {
        if (kt + 1 < NK) asm volatile("cp.async.wait_group 1;\n");
        else             asm volatile("cp.async.wait_group 0;\n");
        __syncthreads();

        const uint32_t* As = &smbuf[(kt & 1) * GSTAGE];
        const uint32_t* Bs = As + 128 * GP;

#pragma unroll
        for (int kk = 0; kk < 32; kk += 8) {
            uint32_t af[4][4], bf[4][2];
#pragma unroll
            for (int mi = 0; mi < 4; mi++) {
                const int r = wm + mi * 16 + g;
                af[mi][0] = As[r * GP + kk + tg];
                af[mi][1] = As[(r + 8) * GP + kk + tg];
                af[mi][2] = As[r * GP + kk + tg + 4];
                af[mi][3] = As[(r + 8) * GP + kk + tg + 4];
            }
#pragma unroll
            for (int ni = 0; ni < 4; ni++) {
                const int c = wn + ni * 8 + g;
                bf[ni][0] = Bs[c * GP + kk + tg];
                bf[ni][1] = Bs[c * GP + kk + tg + 4];
            }
#pragma unroll
            for (int mi = 0; mi < 4; mi++)
#pragma unroll
                for (int ni = 0; ni < 4; ni++)
                    mma16n8k8(acc[mi][ni], af[mi], bf[ni]);
        }

        __syncthreads();
        if (kt + 2 < NK) issue((kt + 2) * 32, kt & 1);
    }
}

// ---------------------------------------------------------------------------
// Fused Q/K/V projection GEMM: blockIdx.z selects (input, weight, bias, dst).
// Writes head-major [B,H,S,dh].
// ---------------------------------------------------------------------------
__global__ void __launch_bounds__(256, 2)
gemm_qkv(const float* __restrict__ Qin, const float* __restrict__ Kin,
         const float* __restrict__ Vin,
         const float* __restrict__ Wq, const float* __restrict__ Wk,
         const float* __restrict__ Wv,
         const float* __restrict__ bq, const float* __restrict__ bk,
         const float* __restrict__ bv)
{
    extern __shared__ uint32_t smbuf[];
    const uint32_t sbase = (uint32_t)__cvta_generic_to_shared(smbuf);

    const int mode = blockIdx.z;
    const float* A    = (mode == 0) ? Qin : (mode == 1) ? Kin : Vin;
    const float* W    = (mode == 0) ? Wq  : (mode == 1) ? Wk  : Wv;
    const float* bias = (mode == 0) ? bq  : (mode == 1) ? bk  : bv;
    float* out        = (mode == 0) ? g_q : (mode == 1) ? g_k : g_v;

    const int m0 = blockIdx.y * 128;
    const int n0 = blockIdx.x * 128;

    float acc[4][4][4];
    gemm_mainloop(A, W, m0, n0, smbuf, sbase, acc);

    const int lane = threadIdx.x & 31;
    const int warp = threadIdx.x >> 5;
    const int wm = (warp & 1) * 64, wn = (warp >> 1) * 32;
    const int g = lane >> 2, tg = lane & 3;

#pragma unroll
    for (int mi = 0; mi < 4; mi++)
#pragma unroll
        for (int ni = 0; ni < 4; ni++)
#pragma unroll
            for (int h = 0; h < 2; h++) {
                const int m = m0 + wm + mi * 16 + g + h * 8;
                const int n = n0 + wn + ni * 8 + tg * 2;
                const int bI = m >> 11, s = m & 2047;
                const int head = n >> 6, dd = n & 63;
                float2 val;
                val.x = acc[mi][ni][h * 2 + 0] + bias[n];
                val.y = acc[mi][ni][h * 2 + 1] + bias[n + 1];
                *(float2*)&out[((size_t)(bI * H_SZ + head) << 17)
                               + ((size_t)s << 6) + dd] = val;
            }
}

// ---------------------------------------------------------------------------
// Output projection GEMM: x = g_ctx @ Wo^T + bo + resid, row-major into g_q.
// ---------------------------------------------------------------------------
__global__ void __launch_bounds__(256, 2)
gemm_o(const float* __restrict__ Wo, const float* __restrict__ bo,
       const float* __restrict__ resid)
{
    extern __shared__ uint32_t smbuf[];
    const uint32_t sbase = (uint32_t)__cvta_generic_to_shared(smbuf);

    const int m0 = blockIdx.y * 128;
    const int n0 = blockIdx.x * 128;

    float acc[4][4][4];
    gemm_mainloop((const float*)g_ctx, Wo, m0, n0, smbuf, sbase, acc);

    const int lane = threadIdx.x & 31;
    const int warp = threadIdx.x >> 5;
    const int wm = (warp & 1) * 64, wn = (warp >> 1) * 32;
    const int g = lane >> 2, tg = lane & 3;

#pragma unroll
    for (int mi = 0; mi < 4; mi++)
#pragma unroll
        for (int ni = 0; ni < 4; ni++)
#pragma unroll
            for (int h = 0; h < 2; h++) {
                const int m = m0 + wm + mi * 16 + g + h * 8;
                const int n = n0 + wn + ni * 8 + tg * 2;
                const size_t idx = (size_t)m * D_SZ + n;
                const float2 r2 = *(const float2*)&resid[idx];
                float2 val;
                val.x = acc[mi][ni][h * 2 + 0] + bo[n]     + r2.x;
                val.y = acc[mi][ni][h * 2 + 1] + bo[n + 1] + r2.y;
                *(float2*)&g_q[idx] = val;
            }
}

// ---------------------------------------------------------------------------
// Flash attention, tf32 mma, cp.async double-buffered (unchanged, round 6).
// ---------------------------------------------------------------------------
__global__ void __launch_bounds__(256, 2)
flash_mma(const int* __restrict__ mask)
{
    extern __shared__ uint32_t smbuf[];

    const int b    = blockIdx.z;
    const int h    = blockIdx.y;
    const int q0   = blockIdx.x * 128;
    const int tid  = threadIdx.x;
    const int lane = tid & 31;
    const int warp = tid >> 5;
    const int g    = lane >> 2;
    const int tg   = lane & 3;

    const size_t bh = (size_t)(b * H_SZ + h) * (S_SZ * DH_SZ);
    const uint32_t sbase = (uint32_t)__cvta_generic_to_shared(smbuf);

    {
        const float4* gq = (const float4*)(g_q + bh + (size_t)q0 * DH_SZ);
        for (int idx = tid; idx < 2048; idx += 256) {
            const int r = idx >> 4, c = (idx & 15) << 2;
            const uint32_t off = (r < 64) ? (r * PK + c)
                                          : (64 * PK + (r - 64) * PV + c);
            cp16(sbase + off * 4, gq + idx);
        }
        asm volatile("cp.async.commit_group;\n");
        asm volatile("cp.async.wait_group 0;\n");
        __syncthreads();
    }

    uint32_t qf[8][4];
    {
        const int r = warp * 16 + g;
        const uint32_t* b0 = (r < 64) ? &smbuf[r * PK]
                                      : &smbuf[64 * PK + (r - 64) * PV];
        const int r1 = r + 8;
        const uint32_t* b1 = (r1 < 64) ? &smbuf[r1 * PK]
                                       : &smbuf[64 * PK + (r1 - 64) * PV];
#pragma unroll
        for (int k8 = 0; k8 < 8; k8++) {
            const int k = k8 * 8;
            qf[k8][0] = f2tf32(0.125f * __uint_as_float(b0[k + tg]));
            qf[k8][1] = f2tf32(0.125f * __uint_as_float(b1[k + tg]));
            qf[k8][2] = f2tf32(0.125f * __uint_as_float(b0[k + tg + 4]));
            qf[k8][3] = f2tf32(0.125f * __uint_as_float(b1[k + tg + 4]));
        }
    }
    __syncthreads();

    const float4* gkb = (const float4*)(g_k + bh);
    const float4* gvb = (const float4*)(g_v + bh);

    auto issue_tile = [&](int t, int stage) {
        const uint32_t kb = sbase + (stage * STAGE_W) * 4;
        const uint32_t vb = kb + (64 * PK) * 4;
        const float4* gk = gkb + (size_t)t * 1024;
        const float4* gv = gvb + (size_t)t * 1024;
#pragma unroll
        for (int u = 0; u < 4; u++) {
            const int idx = tid + 256 * u;
            const int r = idx >> 4, c = (idx & 15) << 2;
            cp16(kb + (r * PK + c) * 4, gk + idx);
            cp16(vb + (r * PV + c) * 4, gv + idx);
        }
        asm volatile("cp.async.commit_group;\n");
    };

    issue_tile(0, 0);
    issue_tile(1, 1);

    float of[8][4];
#pragma unroll
    for (int ni = 0; ni < 8; ni++)
#pragma unroll
        for (int c = 0; c < 4; c++) of[ni][c] = 0.f;
    float m0 = -1e30f, m1 = -1e30f, l0 = 0.f, l1 = 0.f;

    const int* mrow = mask + b * S_SZ;
    const int NT = S_SZ / 64;

    for (int t = 0; t < NT; t++) {
        if (t + 1 < NT) asm volatile("cp.async.wait_group 1;\n");
        else            asm volatile("cp.async.wait_group 0;\n");
        __syncthreads();

        const uint32_t* KsS = &smbuf[(t & 1) * STAGE_W];
        const uint32_t* VsS = KsS + 64 * PK;

        float s_[8][4];
#pragma unroll
        for (int nt = 0; nt < 8; nt++) {
            s_[nt][0] = 0.f; s_[nt][1] = 0.f; s_[nt][2] = 0.f; s_[nt][3] = 0.f;
#pragma unroll
            for (int k8 = 0; k8 < 8; k8++) {
                uint32_t bf[2];
                bf[0] = KsS[(nt * 8 + g) * PK + k8 * 8 + tg];
                bf[1] = KsS[(nt * 8 + g) * PK + k8 * 8 + tg + 4];
                mma16n8k8(s_[nt], qf[k8], bf);
            }
        }

#pragma unroll
        for (int nt = 0; nt < 8; nt++) {
            const int mc = t * 64 + nt * 8 + tg * 2;
            const float ma = (mrow[mc]     == 0) ? -1e9f : 0.f;
            const float mb = (mrow[mc + 1] == 0) ? -1e9f : 0.f;
            s_[nt][0] += ma; s_[nt][1] += mb;
            s_[nt][2] += ma; s_[nt][3] += mb;
        }

        float rm0 = -1e30f, rm1 = -1e30f;
#pragma unroll
        for (int nt = 0; nt < 8; nt++) {
            rm0 = fmaxf(rm0, fmaxf(s_[nt][0], s_[nt][1]));
            rm1 = fmaxf(rm1, fmaxf(s_[nt][2], s_[nt][3]));
        }
        rm0 = fmaxf(rm0, __shfl_xor_sync(0xffffffffu, rm0, 1));
        rm0 = fmaxf(rm0, __shfl_xor_sync(0xffffffffu, rm0, 2));
        rm1 = fmaxf(rm1, __shfl_xor_sync(0xffffffffu, rm1, 1));
        rm1 = fmaxf(rm1, __shfl_xor_sync(0xffffffffu, rm1, 2));

        const float mn0 = fmaxf(m0, rm0);
        const float mn1 = fmaxf(m1, rm1);
        const float al0 = __expf(m0 - mn0);
        const float al1 = __expf(m1 - mn1);
        m0 = mn0; m1 = mn1;

        float rs0 = 0.f, rs1 = 0.f;
#pragma unroll
        for (int nt = 0; nt < 8; nt++) {
            s_[nt][0] = __expf(s_[nt][0] - mn0);
            s_[nt][1] = __expf(s_[nt][1] - mn0);
            s_[nt][2] = __expf(s_[nt][2] - mn1);
            s_[nt][3] = __expf(s_[nt][3] - mn1);
            rs0 += s_[nt][0] + s_[nt][1];
            rs1 += s_[nt][2] + s_[nt][3];
        }
        rs0 += __shfl_xor_sync(0xffffffffu, rs0, 1);
        rs0 += __shfl_xor_sync(0xffffffffu, rs0, 2);
        rs1 += __shfl_xor_sync(0xffffffffu, rs1, 1);
        rs1 += __shfl_xor_sync(0xffffffffu, rs1, 2);
        l0 = l0 * al0 + rs0;
        l1 = l1 * al1 + rs1;

#pragma unroll
        for (int ni = 0; ni < 8; ni++) {
            of[ni][0] *= al0; of[ni][1] *= al0;
            of[ni][2] *= al1; of[ni][3] *= al1;
        }

        const int srcA = (lane & ~3) | (tg >> 1);
        const int srcB = srcA + 2;
        const bool odd = (tg & 1);
#pragma unroll
        for (int j = 0; j < 8; j++) {
            const float x0 = __shfl_sync(0xffffffffu, s_[j][0], srcA);
            const float x1 = __shfl_sync(0xffffffffu, s_[j][1], srcA);
            const float y0 = __shfl_sync(0xffffffffu, s_[j][2], srcA);
            const float y1 = __shfl_sync(0xffffffffu, s_[j][3], srcA);
            const float x2 = __shfl_sync(0xffffffffu, s_[j][0], srcB);
            const float x3 = __shfl_sync(0xffffffffu, s_[j][1], srcB);
            const float y2 = __shfl_sync(0xffffffffu, s_[j][2], srcB);
            const float y3 = __shfl_sync(0xffffffffu, s_[j][3], srcB);
            uint32_t pa[4];
            pa[0] = __float_as_uint(odd ? x1 : x0);
            pa[1] = __float_as_uint(odd ? y1 : y0);
            pa[2] = __float_as_uint(odd ? x3 : x2);
            pa[3] = __float_as_uint(odd ? y3 : y2);
#pragma unroll
            for (int ni = 0; ni < 8; ni++) {
                uint32_t bf[2];
                bf[0] = VsS[(j * 8 + tg) * PV + ni * 8 + g];
                bf[1] = VsS[(j * 8 + tg + 4) * PV + ni * 8 + g];
                mma16n8k8(of[ni], pa, bf);
            }
        }

        __syncthreads();
        if (t + 2 < NT) issue_tile(t + 2, t & 1);
    }

    const float il0 = 1.f / l0;
    const float il1 = 1.f / l1;
    const int row0 = b * S_SZ + q0 + warp * 16 + g;
    const int colb = h * DH_SZ;
#pragma unroll
    for (int ni = 0; ni < 8; ni++) {
        const int col = colb + ni * 8 + tg * 2;
        float2 v0, v1;
        v0.x = of[ni][0] * il0; v0.y = of[ni][1] * il0;
        v1.x = of[ni][2] * il1; v1.y = of[ni][3] * il1;
        *(float2*)&g_ctx[(size_t)row0 * D_SZ + col]       = v0;
        *(float2*)&g_ctx[(size_t)(row0 + 8) * D_SZ + col] = v1;
    }
}

// ---------------------------------------------------------------------------
// LayerNorm over last dim (1024). One block per row, two-pass (exact).
// ---------------------------------------------------------------------------
__global__ void __launch_bounds__(256)
ln_kernel(const float* __restrict__ gamma, const float* __restrict__ beta,
          float* __restrict__ out)
{
    __shared__ float red[8];
    const int row = blockIdx.x;
    const int tid = threadIdx.x;
    const float* xr = g_q + (size_t)row * D_SZ;

    float v[4];
#pragma unroll
    for (int u = 0; u < 4; u++) v[u] = xr[tid + 256 * u];

    float s = v[0] + v[1] + v[2] + v[3];
#pragma unroll
    for (int off = 16; off > 0; off >>= 1)
        s += __shfl_xor_sync(0xffffffffu, s, off);
    if ((tid & 31) == 0) red[tid >> 5] = s;
    __syncthreads();
    float tot = 0.f;
#pragma unroll
    for (int w = 0; w < 8; w++) tot += red[w];
    const float mu = tot * (1.f / 1024.f);

    float d0 = v[0] - mu, d1 = v[1] - mu, d2 = v[2] - mu, d3 = v[3] - mu;
    float ss = d0 * d0 + d1 * d1 + d2 * d2 + d3 * d3;
#pragma unroll
    for (int off = 16; off > 0; off >>= 1)
        ss += __shfl_xor_sync(0xffffffffu, ss, off);
    __syncthreads();
    if ((tid & 31) == 0) red[tid >> 5] = ss;
    __syncthreads();
    float vtot = 0.f;
#pragma unroll
    for (int w = 0; w < 8; w++) vtot += red[w];
    const float inv = rsqrtf(vtot * (1.f / 1024.f) + 1e-5f);

#pragma unroll
    for (int u = 0; u < 4; u++) {
        const int c = tid + 256 * u;
        out[(size_t)row * D_SZ + c] = gamma[c] * (v[u] - mu) * inv + beta[c];
    }
}

// ---------------------------------------------------------------------------
extern "C" void kernel_launch(void* const* d_in, const int* in_sizes, int n_in,
                              void* d_out, int out_size)
{
    const float* Q     = (const float*)d_in[0];
    const float* K     = (const float*)d_in[1];
    const float* V     = (const float*)d_in[2];
    const int*   mask  = (const int*)  d_in[3];
    const float* Wq    = (const float*)d_in[4];
    const float* bq    = (const float*)d_in[5];
    const float* Wk    = (const float*)d_in[6];
    const float* bk    = (const float*)d_in[7];
    const float* Wv    = (const float*)d_in[8];
    const float* bv    = (const float*)d_in[9];
    const float* Wo    = (const float*)d_in[10];
    const float* bo    = (const float*)d_in[11];
    const float* gamma = (const float*)d_in[12];
    const float* beta  = (const float*)d_in[13];
    float* out = (float*)d_out;

    // Capture-safe (not stream ops); clear any sticky benign error.
    cudaFuncSetAttribute(flash_mma,
                         cudaFuncAttributeMaxDynamicSharedMemorySize,
                         FLASH_SMEM_B);
    cudaFuncSetAttribute(gemm_qkv,
                         cudaFuncAttributeMaxDynamicSharedMemorySize,
                         GEMM_SMEM_B);
    cudaFuncSetAttribute(gemm_o,
                         cudaFuncAttributeMaxDynamicSharedMemorySize,
                         GEMM_SMEM_B);
    (void)cudaGetLastError();

    const dim3 qkv_grid(D_SZ / 128, M_SZ / 128, 3);   // (8, 64, 3)
    const dim3 o_grid(D_SZ / 128, M_SZ / 128);        // (8, 64)

    gemm_qkv<<<qkv_grid, 256, GEMM_SMEM_B>>>(Q, K, V, Wq, Wk, Wv, bq, bk, bv);

    flash_mma<<<dim3(S_SZ / 128, H_SZ, B_SZ), 256, FLASH_SMEM_B>>>(mask);

    gemm_o<<<o_grid, 256, GEMM_SMEM_B>>>(Wo, bo, Q);

    ln_kernel<<<M_SZ, 256>>>(gamma, beta, out);
}

// round 9
// speedup vs baseline: 4.5063x; 1.0740x over previous
#include <cuda_runtime.h>
#include <cstdint>
#include <cstddef>

// ---------------------------------------------------------------------------
// MultiHeadAttention fused block (round 8: ldmatrix fragment loads).
// ---------------------------------------------------------------------------

#define B_SZ   4
#define S_SZ   2048
#define D_SZ   1024
#define H_SZ   16
#define DH_SZ  64
#define M_SZ   (B_SZ * S_SZ)          // 8192

#define PK 68   // flash Ks pitch: 68 % 32 == 4 -> conflict-free ldmatrix rows
#define PV 72   // flash Vs pitch: 72 % 32 == 8 -> PV B-frag conflict-free
#define STAGE_W (64 * PK + 64 * PV)
#define FLASH_SMEM_B (2 * STAGE_W * 4)

#define GP 36                          // gemm smem pitch (36 % 32 == 4)
#define GSTAGE (128 * GP * 2)
#define GEMM_SMEM_B (2 * GSTAGE * 4)   // 73728 bytes

__device__ float g_q[M_SZ * D_SZ];
__device__ float g_k[M_SZ * D_SZ];
__device__ float g_v[M_SZ * D_SZ];
__device__ float g_ctx[M_SZ * D_SZ];

__device__ __forceinline__ uint32_t f2tf32(float x) {
    uint32_t r;
    asm("cvt.rna.tf32.f32 %0, %1;" : "=r"(r) : "f"(x));
    return r;
}

__device__ __forceinline__ void mma16n8k8(float c[4], const uint32_t a[4],
                                          const uint32_t b[2]) {
    asm volatile(
        "mma.sync.aligned.m16n8k8.row.col.f32.tf32.tf32.f32 "
        "{%0,%1,%2,%3}, {%4,%5,%6,%7}, {%8,%9}, {%0,%1,%2,%3};\n"
        : "+f"(c[0]), "+f"(c[1]), "+f"(c[2]), "+f"(c[3])
        : "r"(a[0]), "r"(a[1]), "r"(a[2]), "r"(a[3]), "r"(b[0]), "r"(b[1]));
}

__device__ __forceinline__ void cp16(uint32_t smem_dst, const void* gmem_src) {
    asm volatile("cp.async.cg.shared.global [%0], [%1], 16;\n"
                 :: "r"(smem_dst), "l"(gmem_src));
}

__device__ __forceinline__ void ldsm_x4(uint32_t d[4], uint32_t addr) {
    asm volatile("ldmatrix.sync.aligned.m8n8.x4.shared.b16 {%0,%1,%2,%3}, [%4];"
                 : "=r"(d[0]), "=r"(d[1]), "=r"(d[2]), "=r"(d[3]) : "r"(addr));
}

// ---------------------------------------------------------------------------
// Pipelined tf32 GEMM mainloop, ldmatrix fragment loads.
// ---------------------------------------------------------------------------
__device__ __forceinline__ void gemm_mainloop(
    const float* __restrict__ A, const float* __restrict__ W,
    int m0, int n0, uint32_t sbase, float acc[4][4][4])
{
    const int tid  = threadIdx.x;
    const int lane = tid & 31;
    const int warp = tid >> 5;
    const int wm   = (warp & 1) * 64;
    const int wn   = (warp >> 1) * 32;
    const int lm8  = lane & 7;          // ldmatrix row within matrix
    const int m4   = lane >> 3;         // ldmatrix matrix index
    const int lr   = tid >> 3;
    const int lc   = (tid & 7) << 2;

#pragma unroll
    for (int mi = 0; mi < 4; mi++)
#pragma unroll
        for (int ni = 0; ni < 4; ni++)
#pragma unroll
            for (int c = 0; c < 4; c++) acc[mi][ni][c] = 0.f;

    auto issue = [&](int k0, int stage) {
        const uint32_t ab = sbase + (stage * GSTAGE) * 4;
        const uint32_t bb = ab + (128 * GP) * 4;
#pragma unroll
        for (int u = 0; u < 4; u++) {
            const int row = lr + 32 * u;
            cp16(ab + (row * GP + lc) * 4, A + (size_t)(m0 + row) * D_SZ + k0 + lc);
            cp16(bb + (row * GP + lc) * 4, W + (size_t)(n0 + row) * D_SZ + k0 + lc);
        }
        asm volatile("cp.async.commit_group;\n");
    };

    issue(0, 0);
    issue(32, 1);

    // ldmatrix lane-address components
    const int a_row = (m4 & 1) * 8 + lm8;        // + wm + mi*16
    const int a_col = (m4 >> 1) * 4;             // + kk
    const int b_row = (m4 >> 1) * 8 + lm8;       // + wn + np*8
    const int b_col = (m4 & 1) * 4;              // + kk

    const int NK = D_SZ / 32;
    for (int kt = 0; kt < NK; kt++) {
        if (kt + 1 < NK) asm volatile("cp.async.wait_group 1;\n");
        else             asm volatile("cp.async.wait_group 0;\n");
        __syncthreads();

        const uint32_t aw = sbase + ((kt & 1) * GSTAGE) * 4;
        const uint32_t bw = aw + (128 * GP) * 4;

#pragma unroll
        for (int kk = 0; kk < 32; kk += 8) {
            uint32_t af[4][4], bf[4][2];
#pragma unroll
            for (int mi = 0; mi < 4; mi++)
                ldsm_x4(af[mi],
                        aw + ((wm + mi * 16 + a_row) * GP + kk + a_col) * 4);
#pragma unroll
            for (int np = 0; np < 4; np += 2)
                ldsm_x4(&bf[np][0],
                        bw + ((wn + np * 8 + b_row) * GP + kk + b_col) * 4);
#pragma unroll
            for (int mi = 0; mi < 4; mi++)
#pragma unroll
                for (int ni = 0; ni < 4; ni++)
                    mma16n8k8(acc[mi][ni], af[mi], bf[ni]);
        }

        __syncthreads();
        if (kt + 2 < NK) issue((kt + 2) * 32, kt & 1);
    }
}

// ---------------------------------------------------------------------------
// Fused Q/K/V projection GEMM.
// ---------------------------------------------------------------------------
__global__ void __launch_bounds__(256, 2)
gemm_qkv(const float* __restrict__ Qin, const float* __restrict__ Kin,
         const float* __restrict__ Vin,
         const float* __restrict__ Wq, const float* __restrict__ Wk,
         const float* __restrict__ Wv,
         const float* __restrict__ bq, const float* __restrict__ bk,
         const float* __restrict__ bv)
{
    extern __shared__ uint32_t smbuf[];
    const uint32_t sbase = (uint32_t)__cvta_generic_to_shared(smbuf);

    const int mode = blockIdx.z;
    const float* A    = (mode == 0) ? Qin : (mode == 1) ? Kin : Vin;
    const float* W    = (mode == 0) ? Wq  : (mode == 1) ? Wk  : Wv;
    const float* bias = (mode == 0) ? bq  : (mode == 1) ? bk  : bv;
    float* out        = (mode == 0) ? g_q : (mode == 1) ? g_k : g_v;

    const int m0 = blockIdx.y * 128;
    const int n0 = blockIdx.x * 128;

    float acc[4][4][4];
    gemm_mainloop(A, W, m0, n0, sbase, acc);

    const int lane = threadIdx.x & 31;
    const int warp = threadIdx.x >> 5;
    const int wm = (warp & 1) * 64, wn = (warp >> 1) * 32;
    const int g = lane >> 2, tg = lane & 3;

#pragma unroll
    for (int mi = 0; mi < 4; mi++)
#pragma unroll
        for (int ni = 0; ni < 4; ni++)
#pragma unroll
            for (int h = 0; h < 2; h++) {
                const int m = m0 + wm + mi * 16 + g + h * 8;
                const int n = n0 + wn + ni * 8 + tg * 2;
                const int bI = m >> 11, s = m & 2047;
                const int head = n >> 6, dd = n & 63;
                float2 val;
                val.x = acc[mi][ni][h * 2 + 0] + bias[n];
                val.y = acc[mi][ni][h * 2 + 1] + bias[n + 1];
                *(float2*)&out[((size_t)(bI * H_SZ + head) << 17)
                               + ((size_t)s << 6) + dd] = val;
            }
}

// ---------------------------------------------------------------------------
// Output projection GEMM: x = g_ctx @ Wo^T + bo + resid -> g_q.
// ---------------------------------------------------------------------------
__global__ void __launch_bounds__(256, 2)
gemm_o(const float* __restrict__ Wo, const float* __restrict__ bo,
       const float* __restrict__ resid)
{
    extern __shared__ uint32_t smbuf[];
    const uint32_t sbase = (uint32_t)__cvta_generic_to_shared(smbuf);

    const int m0 = blockIdx.y * 128;
    const int n0 = blockIdx.x * 128;

    float acc[4][4][4];
    gemm_mainloop((const float*)g_ctx, Wo, m0, n0, sbase, acc);

    const int lane = threadIdx.x & 31;
    const int warp = threadIdx.x >> 5;
    const int wm = (warp & 1) * 64, wn = (warp >> 1) * 32;
    const int g = lane >> 2, tg = lane & 3;

#pragma unroll
    for (int mi = 0; mi < 4; mi++)
#pragma unroll
        for (int ni = 0; ni < 4; ni++)
#pragma unroll
            for (int h = 0; h < 2; h++) {
                const int m = m0 + wm + mi * 16 + g + h * 8;
                const int n = n0 + wn + ni * 8 + tg * 2;
                const size_t idx = (size_t)m * D_SZ + n;
                const float2 r2 = *(const float2*)&resid[idx];
                float2 val;
                val.x = acc[mi][ni][h * 2 + 0] + bo[n]     + r2.x;
                val.y = acc[mi][ni][h * 2 + 1] + bo[n + 1] + r2.y;
                *(float2*)&g_q[idx] = val;
            }
}

// ---------------------------------------------------------------------------
// Flash attention, tf32 mma, cp.async double-buffered, ldmatrix K-frags.
// ---------------------------------------------------------------------------
__global__ void __launch_bounds__(256, 2)
flash_mma(const int* __restrict__ mask)
{
    extern __shared__ uint32_t smbuf[];

    const int b    = blockIdx.z;
    const int h    = blockIdx.y;
    const int q0   = blockIdx.x * 128;
    const int tid  = threadIdx.x;
    const int lane = tid & 31;
    const int warp = tid >> 5;
    const int g    = lane >> 2;
    const int tg   = lane & 3;
    const int lm8  = lane & 7;
    const int m4   = lane >> 3;

    const size_t bh = (size_t)(b * H_SZ + h) * (S_SZ * DH_SZ);
    const uint32_t sbase = (uint32_t)__cvta_generic_to_shared(smbuf);

    {
        const float4* gq = (const float4*)(g_q + bh + (size_t)q0 * DH_SZ);
        for (int idx = tid; idx < 2048; idx += 256) {
            const int r = idx >> 4, c = (idx & 15) << 2;
            const uint32_t off = (r < 64) ? (r * PK + c)
                                          : (64 * PK + (r - 64) * PV + c);
            cp16(sbase + off * 4, gq + idx);
        }
        asm volatile("cp.async.commit_group;\n");
        asm volatile("cp.async.wait_group 0;\n");
        __syncthreads();
    }

    uint32_t qf[8][4];
    {
        const int r = warp * 16 + g;
        const uint32_t* b0 = (r < 64) ? &smbuf[r * PK]
                                      : &smbuf[64 * PK + (r - 64) * PV];
        const int r1 = r + 8;
        const uint32_t* b1 = (r1 < 64) ? &smbuf[r1 * PK]
                                       : &smbuf[64 * PK + (r1 - 64) * PV];
#pragma unroll
        for (int k8 = 0; k8 < 8; k8++) {
            const int k = k8 * 8;
            qf[k8][0] = f2tf32(0.125f * __uint_as_float(b0[k + tg]));
            qf[k8][1] = f2tf32(0.125f * __uint_as_float(b1[k + tg]));
            qf[k8][2] = f2tf32(0.125f * __uint_as_float(b0[k + tg + 4]));
            qf[k8][3] = f2tf32(0.125f * __uint_as_float(b1[k + tg + 4]));
        }
    }
    __syncthreads();

    const float4* gkb = (const float4*)(g_k + bh);
    const float4* gvb = (const float4*)(g_v + bh);

    auto issue_tile = [&](int t, int stage) {
        const uint32_t kb = sbase + (stage * STAGE_W) * 4;
        const uint32_t vb = kb + (64 * PK) * 4;
        const float4* gk = gkb + (size_t)t * 1024;
        const float4* gv = gvb + (size_t)t * 1024;
#pragma unroll
        for (int u = 0; u < 4; u++) {
            const int idx = tid + 256 * u;
            const int r = idx >> 4, c = (idx & 15) << 2;
            cp16(kb + (r * PK + c) * 4, gk + idx);
            cp16(vb + (r * PV + c) * 4, gv + idx);
        }
        asm volatile("cp.async.commit_group;\n");
    };

    issue_tile(0, 0);
    issue_tile(1, 1);

    float of[8][4];
#pragma unroll
    for (int ni = 0; ni < 8; ni++)
#pragma unroll
        for (int c = 0; c < 4; c++) of[ni][c] = 0.f;
    float m0 = -1e30f, m1 = -1e30f, l0 = 0.f, l1 = 0.f;

    const int* mrow = mask + b * S_SZ;
    const int NT = S_SZ / 64;

    // ldmatrix K-frag lane address: row within nt-group, col block
    const int kq_col = (m4 >> 1) * 8 + (m4 & 1) * 4;   // + k8g*16

    for (int t = 0; t < NT; t++) {
        if (t + 1 < NT) asm volatile("cp.async.wait_group 1;\n");
        else            asm volatile("cp.async.wait_group 0;\n");
        __syncthreads();

        const uint32_t kwb = sbase + ((t & 1) * STAGE_W) * 4;
        const uint32_t* VsS = &smbuf[(t & 1) * STAGE_W + 64 * PK];

        // S = (Q/8) K^T, ldmatrix.x4 loads 2 k8-groups of B-frags at once
        float s_[8][4];
#pragma unroll
        for (int nt = 0; nt < 8; nt++) {
            s_[nt][0] = 0.f; s_[nt][1] = 0.f; s_[nt][2] = 0.f; s_[nt][3] = 0.f;
#pragma unroll
            for (int k8g = 0; k8g < 4; k8g++) {
                uint32_t d[4];
                ldsm_x4(d, kwb + ((nt * 8 + lm8) * PK + k8g * 16 + kq_col) * 4);
                mma16n8k8(s_[nt], qf[2 * k8g],     &d[0]);
                mma16n8k8(s_[nt], qf[2 * k8g + 1], &d[2]);
            }
        }

#pragma unroll
        for (int nt = 0; nt < 8; nt++) {
            const int mc = t * 64 + nt * 8 + tg * 2;
            const float ma = (mrow[mc]     == 0) ? -1e9f : 0.f;
            const float mb = (mrow[mc + 1] == 0) ? -1e9f : 0.f;
            s_[nt][0] += ma; s_[nt][1] += mb;
            s_[nt][2] += ma; s_[nt][3] += mb;
        }

        float rm0 = -1e30f, rm1 = -1e30f;
#pragma unroll
        for (int nt = 0; nt < 8; nt++) {
            rm0 = fmaxf(rm0, fmaxf(s_[nt][0], s_[nt][1]));
            rm1 = fmaxf(rm1, fmaxf(s_[nt][2], s_[nt][3]));
        }
        rm0 = fmaxf(rm0, __shfl_xor_sync(0xffffffffu, rm0, 1));
        rm0 = fmaxf(rm0, __shfl_xor_sync(0xffffffffu, rm0, 2));
        rm1 = fmaxf(rm1, __shfl_xor_sync(0xffffffffu, rm1, 1));
        rm1 = fmaxf(rm1, __shfl_xor_sync(0xffffffffu, rm1, 2));

        const float mn0 = fmaxf(m0, rm0);
        const float mn1 = fmaxf(m1, rm1);
        const float al0 = __expf(m0 - mn0);
        const float al1 = __expf(m1 - mn1);
        m0 = mn0; m1 = mn1;

        float rs0 = 0.f, rs1 = 0.f;
#pragma unroll
        for (int nt = 0; nt < 8; nt++) {
            s_[nt][0] = __expf(s_[nt][0] - mn0);
            s_[nt][1] = __expf(s_[nt][1] - mn0);
            s_[nt][2] = __expf(s_[nt][2] - mn1);
            s_[nt][3] = __expf(s_[nt][3] - mn1);
            rs0 += s_[nt][0] + s_[nt][1];
            rs1 += s_[nt][2] + s_[nt][3];
        }
        rs0 += __shfl_xor_sync(0xffffffffu, rs0, 1);
        rs0 += __shfl_xor_sync(0xffffffffu, rs0, 2);
        rs1 += __shfl_xor_sync(0xffffffffu, rs1, 1);
        rs1 += __shfl_xor_sync(0xffffffffu, rs1, 2);
        l0 = l0 * al0 + rs0;
        l1 = l1 * al1 + rs1;

#pragma unroll
        for (int ni = 0; ni < 8; ni++) {
            of[ni][0] *= al0; of[ni][1] *= al0;
            of[ni][2] *= al1; of[ni][3] *= al1;
        }

        const int srcA = (lane & ~3) | (tg >> 1);
        const int srcB = srcA + 2;
        const bool odd = (tg & 1);
#pragma unroll
        for (int j = 0; j < 8; j++) {
            const float x0 = __shfl_sync(0xffffffffu, s_[j][0], srcA);
            const float x1 = __shfl_sync(0xffffffffu, s_[j][1], srcA);
            const float y0 = __shfl_sync(0xffffffffu, s_[j][2], srcA);
            const float y1 = __shfl_sync(0xffffffffu, s_[j][3], srcA);
            const float x2 = __shfl_sync(0xffffffffu, s_[j][0], srcB);
            const float x3 = __shfl_sync(0xffffffffu, s_[j][1], srcB);
            const float y2 = __shfl_sync(0xffffffffu, s_[j][2], srcB);
            const float y3 = __shfl_sync(0xffffffffu, s_[j][3], srcB);
            uint32_t pa[4];
            pa[0] = __float_as_uint(odd ? x1 : x0);
            pa[1] = __float_as_uint(odd ? y1 : y0);
            pa[2] = __float_as_uint(odd ? x3 : x2);
            pa[3] = __float_as_uint(odd ? y3 : y2);
#pragma unroll
            for (int ni = 0; ni < 8; ni++) {
                uint32_t bf[2];
                bf[0] = VsS[(j * 8 + tg) * PV + ni * 8 + g];
                bf[1] = VsS[(j * 8 + tg + 4) * PV + ni * 8 + g];
                mma16n8k8(of[ni], pa, bf);
            }
        }

        __syncthreads();
        if (t + 2 < NT) issue_tile(t + 2, t & 1);
    }

    const float il0 = 1.f / l0;
    const float il1 = 1.f / l1;
    const int row0 = b * S_SZ + q0 + warp * 16 + g;
    const int colb = h * DH_SZ;
#pragma unroll
    for (int ni = 0; ni < 8; ni++) {
        const int col = colb + ni * 8 + tg * 2;
        float2 v0, v1;
        v0.x = of[ni][0] * il0; v0.y = of[ni][1] * il0;
        v1.x = of[ni][2] * il1; v1.y = of[ni][3] * il1;
        *(float2*)&g_ctx[(size_t)row0 * D_SZ + col]       = v0;
        *(float2*)&g_ctx[(size_t)(row0 + 8) * D_SZ + col] = v1;
    }
}

// ---------------------------------------------------------------------------
// LayerNorm over last dim (1024). float4 vectorized, two-pass (exact).
// ---------------------------------------------------------------------------
__global__ void __launch_bounds__(256)
ln_kernel(const float* __restrict__ gamma, const float* __restrict__ beta,
          float* __restrict__ out)
{
    __shared__ float red[8];
    const int row = blockIdx.x;
    const int tid = threadIdx.x;
    const float4 v = ((const float4*)(g_q + (size_t)row * D_SZ))[tid];

    float s = v.x + v.y + v.z + v.w;
#pragma unroll
    for (int off = 16; off > 0; off >>= 1)
        s += __shfl_xor_sync(0xffffffffu, s, off);
    if ((tid & 31) == 0) red[tid >> 5] = s;
    __syncthreads();
    float tot = 0.f;
#pragma unroll
    for (int w = 0; w < 8; w++) tot += red[w];
    const float mu = tot * (1.f / 1024.f);

    const float d0 = v.x - mu, d1 = v.y - mu, d2 = v.z - mu, d3 = v.w - mu;
    float ss = d0 * d0 + d1 * d1 + d2 * d2 + d3 * d3;
#pragma unroll
    for (int off = 16; off > 0; off >>= 1)
        ss += __shfl_xor_sync(0xffffffffu, ss, off);
    __syncthreads();
    if ((tid & 31) == 0) red[tid >> 5] = ss;
    __syncthreads();
    float vtot = 0.f;
#pragma unroll
    for (int w = 0; w < 8; w++) vtot += red[w];
    const float inv = rsqrtf(vtot * (1.f / 1024.f) + 1e-5f);

    const float4 ga = ((const float4*)gamma)[tid];
    const float4 be = ((const float4*)beta)[tid];
    float4 o;
    o.x = ga.x * d0 * inv + be.x;
    o.y = ga.y * d1 * inv + be.y;
    o.z = ga.z * d2 * inv + be.z;
    o.w = ga.w * d3 * inv + be.w;
    ((float4*)(out + (size_t)row * D_SZ))[tid] = o;
}

// ---------------------------------------------------------------------------
extern "C" void kernel_launch(void* const* d_in, const int* in_sizes, int n_in,
                              void* d_out, int out_size)
{
    const float* Q     = (const float*)d_in[0];
    const float* K     = (const float*)d_in[1];
    const float* V     = (const float*)d_in[2];
    const int*   mask  = (const int*)  d_in[3];
    const float* Wq    = (const float*)d_in[4];
    const float* bq    = (const float*)d_in[5];
    const float* Wk    = (const float*)d_in[6];
    const float* bk    = (const float*)d_in[7];
    const float* Wv    = (const float*)d_in[8];
    const float* bv    = (const float*)d_in[9];
    const float* Wo    = (const float*)d_in[10];
    const float* bo    = (const float*)d_in[11];
    const float* gamma = (const float*)d_in[12];
    const float* beta  = (const float*)d_in[13];
    float* out = (float*)d_out;

    cudaFuncSetAttribute(flash_mma,
                         cudaFuncAttributeMaxDynamicSharedMemorySize,
                         FLASH_SMEM_B);
    cudaFuncSetAttribute(gemm_qkv,
                         cudaFuncAttributeMaxDynamicSharedMemorySize,
                         GEMM_SMEM_B);
    cudaFuncSetAttribute(gemm_o,
                         cudaFuncAttributeMaxDynamicSharedMemorySize,
                         GEMM_SMEM_B);
    (void)cudaGetLastError();

    const dim3 qkv_grid(D_SZ / 128, M_SZ / 128, 3);
    const dim3 o_grid(D_SZ / 128, M_SZ / 128);

    gemm_qkv<<<qkv_grid, 256, GEMM_SMEM_B>>>(Q, K, V, Wq, Wk, Wv, bq, bk, bv);

    flash_mma<<<dim3(S_SZ / 128, H_SZ, B_SZ), 256, FLASH_SMEM_B>>>(mask);

    gemm_o<<<o_grid, 256, GEMM_SMEM_B>>>(Wo, bo, Q);

    ln_kernel<<<M_SZ, 256>>>(gamma, beta, out);
}

// round 12
// speedup vs baseline: 4.8324x; 1.0724x over previous
#include <cuda_runtime.h>
#include <cstdint>
#include <cstddef>

// ---------------------------------------------------------------------------
// MultiHeadAttention fused block (round 11: revert to mma.sync GEMMs
// [tcgen05 unavailable: harness targets sm_100], flash PV via permuted
// contraction -- zero-shuffle P reuse).
// ---------------------------------------------------------------------------

#define B_SZ   4
#define S_SZ   2048
#define D_SZ   1024
#define H_SZ   16
#define DH_SZ  64
#define M_SZ   (B_SZ * S_SZ)          // 8192

#define PK 68   // K/V pitch (words): 68 % 32 == 4 -> conflict-free everywhere
#define STAGE_W (128 * PK)            // 64 K rows + 64 V rows per stage
#define FLASH_SMEM_B (2 * STAGE_W * 4)

#define GP 36                          // gemm smem pitch (36 % 32 == 4)
#define GSTAGE (128 * GP * 2)
#define GEMM_SMEM_B (2 * GSTAGE * 4)   // 73728 bytes

__device__ float g_q[M_SZ * D_SZ];
__device__ float g_k[M_SZ * D_SZ];
__device__ float g_v[M_SZ * D_SZ];
__device__ float g_ctx[M_SZ * D_SZ];

__device__ __forceinline__ uint32_t f2tf32(float x) {
    uint32_t r;
    asm("cvt.rna.tf32.f32 %0, %1;" : "=r"(r) : "f"(x));
    return r;
}

__device__ __forceinline__ void mma16n8k8(float c[4], const uint32_t a[4],
                                          const uint32_t b[2]) {
    asm volatile(
        "mma.sync.aligned.m16n8k8.row.col.f32.tf32.tf32.f32 "
        "{%0,%1,%2,%3}, {%4,%5,%6,%7}, {%8,%9}, {%0,%1,%2,%3};\n"
        : "+f"(c[0]), "+f"(c[1]), "+f"(c[2]), "+f"(c[3])
        : "r"(a[0]), "r"(a[1]), "r"(a[2]), "r"(a[3]), "r"(b[0]), "r"(b[1]));
}

__device__ __forceinline__ void cp16(uint32_t smem_dst, const void* gmem_src) {
    asm volatile("cp.async.cg.shared.global [%0], [%1], 16;\n"
                 :: "r"(smem_dst), "l"(gmem_src));
}

__device__ __forceinline__ void ldsm_x4(uint32_t d[4], uint32_t addr) {
    asm volatile("ldmatrix.sync.aligned.m8n8.x4.shared.b16 {%0,%1,%2,%3}, [%4];"
                 : "=r"(d[0]), "=r"(d[1]), "=r"(d[2]), "=r"(d[3]) : "r"(addr));
}

// ---------------------------------------------------------------------------
// Pipelined tf32 GEMM mainloop, ldmatrix fragment loads (round 8, proven).
// ---------------------------------------------------------------------------
__device__ __forceinline__ void gemm_mainloop(
    const float* __restrict__ A, const float* __restrict__ W,
    int m0, int n0, uint32_t sbase, float acc[4][4][4])
{
    const int tid  = threadIdx.x;
    const int lane = tid & 31;
    const int warp = tid >> 5;
    const int wm   = (warp & 1) * 64;
    const int wn   = (warp >> 1) * 32;
    const int lm8  = lane & 7;
    const int m4   = lane >> 3;
    const int lr   = tid >> 3;
    const int lc   = (tid & 7) << 2;

#pragma unroll
    for (int mi = 0; mi < 4; mi++)
#pragma unroll
        for (int ni = 0; ni < 4; ni++)
#pragma unroll
            for (int c = 0; c < 4; c++) acc[mi][ni][c] = 0.f;

    auto issue = [&](int k0, int stage) {
        const uint32_t ab = sbase + (stage * GSTAGE) * 4;
        const uint32_t bb = ab + (128 * GP) * 4;
#pragma unroll
        for (int u = 0; u < 4; u++) {
            const int row = lr + 32 * u;
            cp16(ab + (row * GP + lc) * 4, A + (size_t)(m0 + row) * D_SZ + k0 + lc);
            cp16(bb + (row * GP + lc) * 4, W + (size_t)(n0 + row) * D_SZ + k0 + lc);
        }
        asm volatile("cp.async.commit_group;\n");
    };

    issue(0, 0);
    issue(32, 1);

    const int a_row = (m4 & 1) * 8 + lm8;
    const int a_col = (m4 >> 1) * 4;
    const int b_row = (m4 >> 1) * 8 + lm8;
    const int b_col = (m4 & 1) * 4;

    const int NK = D_SZ / 32;
    for (int kt = 0; kt < NK; kt++) {
        if (kt + 1 < NK) asm volatile("cp.async.wait_group 1;\n");
        else             asm volatile("cp.async.wait_group 0;\n");
        __syncthreads();

        const uint32_t aw = sbase + ((kt & 1) * GSTAGE) * 4;
        const uint32_t bw = aw + (128 * GP) * 4;

#pragma unroll
        for (int kk = 0; kk < 32; kk += 8) {
            uint32_t af[4][4], bf[4][2];
#pragma unroll
            for (int mi = 0; mi < 4; mi++)
                ldsm_x4(af[mi],
                        aw + ((wm + mi * 16 + a_row) * GP + kk + a_col) * 4);
#pragma unroll
            for (int np = 0; np < 4; np += 2)
                ldsm_x4(&bf[np][0],
                        bw + ((wn + np * 8 + b_row) * GP + kk + b_col) * 4);
#pragma unroll
            for (int mi = 0; mi < 4; mi++)
#pragma unroll
                for (int ni = 0; ni < 4; ni++)
                    mma16n8k8(acc[mi][ni], af[mi], bf[ni]);
        }

        __syncthreads();
        if (kt + 2 < NK) issue((kt + 2) * 32, kt & 1);
    }
}

// ---------------------------------------------------------------------------
// Fused Q/K/V projection GEMM.
// ---------------------------------------------------------------------------
__global__ void __launch_bounds__(256, 2)
gemm_qkv(const float* __restrict__ Qin, const float* __restrict__ Kin,
         const float* __restrict__ Vin,
         const float* __restrict__ Wq, const float* __restrict__ Wk,
         const float* __restrict__ Wv,
         const float* __restrict__ bq, const float* __restrict__ bk,
         const float* __restrict__ bv)
{
    extern __shared__ uint32_t smbuf[];
    const uint32_t sbase = (uint32_t)__cvta_generic_to_shared(smbuf);

    const int mode = blockIdx.z;
    const float* A    = (mode == 0) ? Qin : (mode == 1) ? Kin : Vin;
    const float* W    = (mode == 0) ? Wq  : (mode == 1) ? Wk  : Wv;
    const float* bias = (mode == 0) ? bq  : (mode == 1) ? bk  : bv;
    float* out        = (mode == 0) ? g_q : (mode == 1) ? g_k : g_v;

    const int m0 = blockIdx.y * 128;
    const int n0 = blockIdx.x * 128;

    float acc[4][4][4];
    gemm_mainloop(A, W, m0, n0, sbase, acc);

    const int lane = threadIdx.x & 31;
    const int warp = threadIdx.x >> 5;
    const int wm = (warp & 1) * 64, wn = (warp >> 1) * 32;
    const int g = lane >> 2, tg = lane & 3;

#pragma unroll
    for (int mi = 0; mi < 4; mi++)
#pragma unroll
        for (int ni = 0; ni < 4; ni++)
#pragma unroll
            for (int h = 0; h < 2; h++) {
                const int m = m0 + wm + mi * 16 + g + h * 8;
                const int n = n0 + wn + ni * 8 + tg * 2;
                const int bI = m >> 11, s = m & 2047;
                const int head = n >> 6, dd = n & 63;
                float2 val;
                val.x = acc[mi][ni][h * 2 + 0] + bias[n];
                val.y = acc[mi][ni][h * 2 + 1] + bias[n + 1];
                *(float2*)&out[((size_t)(bI * H_SZ + head) << 17)
                               + ((size_t)s << 6) + dd] = val;
            }
}

// ---------------------------------------------------------------------------
// Output projection GEMM: x = g_ctx @ Wo^T + bo + resid -> g_q.
// ---------------------------------------------------------------------------
__global__ void __launch_bounds__(256, 2)
gemm_o(const float* __restrict__ Wo, const float* __restrict__ bo,
       const float* __restrict__ resid)
{
    extern __shared__ uint32_t smbuf[];
    const uint32_t sbase = (uint32_t)__cvta_generic_to_shared(smbuf);

    const int m0 = blockIdx.y * 128;
    const int n0 = blockIdx.x * 128;

    float acc[4][4][4];
    gemm_mainloop((const float*)g_ctx, Wo, m0, n0, sbase, acc);

    const int lane = threadIdx.x & 31;
    const int warp = threadIdx.x >> 5;
    const int wm = (warp & 1) * 64, wn = (warp >> 1) * 32;
    const int g = lane >> 2, tg = lane & 3;

#pragma unroll
    for (int mi = 0; mi < 4; mi++)
#pragma unroll
        for (int ni = 0; ni < 4; ni++)
#pragma unroll
            for (int h = 0; h < 2; h++) {
                const int m = m0 + wm + mi * 16 + g + h * 8;
                const int n = n0 + wn + ni * 8 + tg * 2;
                const size_t idx = (size_t)m * D_SZ + n;
                const float2 r2 = *(const float2*)&resid[idx];
                float2 val;
                val.x = acc[mi][ni][h * 2 + 0] + bo[n]     + r2.x;
                val.y = acc[mi][ni][h * 2 + 1] + bo[n + 1] + r2.y;
                *(float2*)&g_q[idx] = val;
            }
}

// ---------------------------------------------------------------------------
// Flash attention, tf32 mma, cp.async double-buffered, ldmatrix K-frags.
// PV uses a permuted contraction: k-slot kappa -> physical kv row p(kappa)
// with p(k)=2k (k<4), p(k)=2(k-4)+1 (k>=4). Then the S C-fragment IS the
// PV A-fragment reordered {c0,c2,c1,c3} (zero shuffles), and V B-frags read
// rows {2tg, 2tg+1}. Pitch PK=68 keeps those reads conflict-free.
// ---------------------------------------------------------------------------
__global__ void __launch_bounds__(256, 2)
flash_mma(const int* __restrict__ mask)
{
    extern __shared__ uint32_t smbuf[];

    const int b    = blockIdx.z;
    const int h    = blockIdx.y;
    const int q0   = blockIdx.x * 128;
    const int tid  = threadIdx.x;
    const int lane = tid & 31;
    const int warp = tid >> 5;
    const int g    = lane >> 2;
    const int tg   = lane & 3;
    const int lm8  = lane & 7;
    const int m4   = lane >> 3;

    const size_t bh = (size_t)(b * H_SZ + h) * (S_SZ * DH_SZ);
    const uint32_t sbase = (uint32_t)__cvta_generic_to_shared(smbuf);

    // Stage 128 Q rows (raw bits) into stage 0 (contiguous pitch-68 region)
    {
        const float4* gq = (const float4*)(g_q + bh + (size_t)q0 * DH_SZ);
        for (int idx = tid; idx < 2048; idx += 256) {
            const int r = idx >> 4, c = (idx & 15) << 2;
            cp16(sbase + (r * PK + c) * 4, gq + idx);
        }
        asm volatile("cp.async.commit_group;\n");
        asm volatile("cp.async.wait_group 0;\n");
        __syncthreads();
    }

    uint32_t qf[8][4];
    {
        const int r = warp * 16 + g;
        const uint32_t* b0 = &smbuf[r * PK];
        const uint32_t* b1 = &smbuf[(r + 8) * PK];
#pragma unroll
        for (int k8 = 0; k8 < 8; k8++) {
            const int k = k8 * 8;
            qf[k8][0] = f2tf32(0.125f * __uint_as_float(b0[k + tg]));
            qf[k8][1] = f2tf32(0.125f * __uint_as_float(b1[k + tg]));
            qf[k8][2] = f2tf32(0.125f * __uint_as_float(b0[k + tg + 4]));
            qf[k8][3] = f2tf32(0.125f * __uint_as_float(b1[k + tg + 4]));
        }
    }
    __syncthreads();

    const float4* gkb = (const float4*)(g_k + bh);
    const float4* gvb = (const float4*)(g_v + bh);

    auto issue_tile = [&](int t, int stage) {
        const uint32_t kb = sbase + (stage * STAGE_W) * 4;
        const uint32_t vb = kb + (64 * PK) * 4;
        const float4* gk = gkb + (size_t)t * 1024;
        const float4* gv = gvb + (size_t)t * 1024;
#pragma unroll
        for (int u = 0; u < 4; u++) {
            const int idx = tid + 256 * u;
            const int r = idx >> 4, c = (idx & 15) << 2;
            cp16(kb + (r * PK + c) * 4, gk + idx);
            cp16(vb + (r * PK + c) * 4, gv + idx);
        }
        asm volatile("cp.async.commit_group;\n");
    };

    issue_tile(0, 0);
    issue_tile(1, 1);

    float of[8][4];
#pragma unroll
    for (int ni = 0; ni < 8; ni++)
#pragma unroll
        for (int c = 0; c < 4; c++) of[ni][c] = 0.f;
    float m0 = -1e30f, m1 = -1e30f, l0 = 0.f, l1 = 0.f;

    const int* mrow = mask + b * S_SZ;
    const int NT = S_SZ / 64;

    const int kq_col = (m4 >> 1) * 8 + (m4 & 1) * 4;

    for (int t = 0; t < NT; t++) {
        if (t + 1 < NT) asm volatile("cp.async.wait_group 1;\n");
        else            asm volatile("cp.async.wait_group 0;\n");
        __syncthreads();

        const uint32_t kwb = sbase + ((t & 1) * STAGE_W) * 4;
        const uint32_t* VsS = &smbuf[(t & 1) * STAGE_W + 64 * PK];

        // S = (Q/8) K^T
        float s_[8][4];
#pragma unroll
        for (int nt = 0; nt < 8; nt++) {
            s_[nt][0] = 0.f; s_[nt][1] = 0.f; s_[nt][2] = 0.f; s_[nt][3] = 0.f;
#pragma unroll
            for (int k8g = 0; k8g < 4; k8g++) {
                uint32_t d[4];
                ldsm_x4(d, kwb + ((nt * 8 + lm8) * PK + k8g * 16 + kq_col) * 4);
                mma16n8k8(s_[nt], qf[2 * k8g],     &d[0]);
                mma16n8k8(s_[nt], qf[2 * k8g + 1], &d[2]);
            }
        }

        // mask (additive), int2 loads
#pragma unroll
        for (int nt = 0; nt < 8; nt++) {
            const int2 mm = *(const int2*)&mrow[t * 64 + nt * 8 + tg * 2];
            const float ma = (mm.x == 0) ? -1e9f : 0.f;
            const float mb = (mm.y == 0) ? -1e9f : 0.f;
            s_[nt][0] += ma; s_[nt][1] += mb;
            s_[nt][2] += ma; s_[nt][3] += mb;
        }

        // online softmax: rows g (c0,c1) and g+8 (c2,c3), quad-lane reduce
        float rm0 = -1e30f, rm1 = -1e30f;
#pragma unroll
        for (int nt = 0; nt < 8; nt++) {
            rm0 = fmaxf(rm0, fmaxf(s_[nt][0], s_[nt][1]));
            rm1 = fmaxf(rm1, fmaxf(s_[nt][2], s_[nt][3]));
        }
        rm0 = fmaxf(rm0, __shfl_xor_sync(0xffffffffu, rm0, 1));
        rm0 = fmaxf(rm0, __shfl_xor_sync(0xffffffffu, rm0, 2));
        rm1 = fmaxf(rm1, __shfl_xor_sync(0xffffffffu, rm1, 1));
        rm1 = fmaxf(rm1, __shfl_xor_sync(0xffffffffu, rm1, 2));

        const float mn0 = fmaxf(m0, rm0);
        const float mn1 = fmaxf(m1, rm1);
        const float al0 = __expf(m0 - mn0);
        const float al1 = __expf(m1 - mn1);
        m0 = mn0; m1 = mn1;

        float rs0 = 0.f, rs1 = 0.f;
#pragma unroll
        for (int nt = 0; nt < 8; nt++) {
            s_[nt][0] = __expf(s_[nt][0] - mn0);
            s_[nt][1] = __expf(s_[nt][1] - mn0);
            s_[nt][2] = __expf(s_[nt][2] - mn1);
            s_[nt][3] = __expf(s_[nt][3] - mn1);
            rs0 += s_[nt][0] + s_[nt][1];
            rs1 += s_[nt][2] + s_[nt][3];
        }
        rs0 += __shfl_xor_sync(0xffffffffu, rs0, 1);
        rs0 += __shfl_xor_sync(0xffffffffu, rs0, 2);
        rs1 += __shfl_xor_sync(0xffffffffu, rs1, 1);
        rs1 += __shfl_xor_sync(0xffffffffu, rs1, 2);
        l0 = l0 * al0 + rs0;
        l1 = l1 * al1 + rs1;

#pragma unroll
        for (int ni = 0; ni < 8; ni++) {
            of[ni][0] *= al0; of[ni][1] *= al0;
            of[ni][2] *= al1; of[ni][3] *= al1;
        }

        // O += P V : permuted contraction, C-frag reused directly as A-frag
#pragma unroll
        for (int j = 0; j < 8; j++) {
            uint32_t pa[4];
            pa[0] = __float_as_uint(s_[j][0]);
            pa[1] = __float_as_uint(s_[j][2]);
            pa[2] = __float_as_uint(s_[j][1]);
            pa[3] = __float_as_uint(s_[j][3]);
            const uint32_t* vr0 = &VsS[(j * 8 + 2 * tg)     * PK];
            const uint32_t* vr1 = &VsS[(j * 8 + 2 * tg + 1) * PK];
#pragma unroll
            for (int ni = 0; ni < 8; ni++) {
                uint32_t bf[2];
                bf[0] = vr0[ni * 8 + g];
                bf[1] = vr1[ni * 8 + g];
                mma16n8k8(of[ni], pa, bf);
            }
        }

        __syncthreads();
        if (t + 2 < NT) issue_tile(t + 2, t & 1);
    }

    const float il0 = 1.f / l0;
    const float il1 = 1.f / l1;
    const int row0 = b * S_SZ + q0 + warp * 16 + g;
    const int colb = h * DH_SZ;
#pragma unroll
    for (int ni = 0; ni < 8; ni++) {
        const int col = colb + ni * 8 + tg * 2;
        float2 v0, v1;
        v0.x = of[ni][0] * il0; v0.y = of[ni][1] * il0;
        v1.x = of[ni][2] * il1; v1.y = of[ni][3] * il1;
        *(float2*)&g_ctx[(size_t)row0 * D_SZ + col]       = v0;
        *(float2*)&g_ctx[(size_t)(row0 + 8) * D_SZ + col] = v1;
    }
}

// ---------------------------------------------------------------------------
// LayerNorm over last dim (1024). float4 vectorized, two-pass (exact).
// ---------------------------------------------------------------------------
__global__ void __launch_bounds__(256)
ln_kernel(const float* __restrict__ gamma, const float* __restrict__ beta,
          float* __restrict__ out)
{
    __shared__ float red[8];
    const int row = blockIdx.x;
    const int tid = threadIdx.x;
    const float4 v = ((const float4*)(g_q + (size_t)row * D_SZ))[tid];

    float s = v.x + v.y + v.z + v.w;
#pragma unroll
    for (int off = 16; off > 0; off >>= 1)
        s += __shfl_xor_sync(0xffffffffu, s, off);
    if ((tid & 31) == 0) red[tid >> 5] = s;
    __syncthreads();
    float tot = 0.f;
#pragma unroll
    for (int w = 0; w < 8; w++) tot += red[w];
    const float mu = tot * (1.f / 1024.f);

    const float d0 = v.x - mu, d1 = v.y - mu, d2 = v.z - mu, d3 = v.w - mu;
    float ss = d0 * d0 + d1 * d1 + d2 * d2 + d3 * d3;
#pragma unroll
    for (int off = 16; off > 0; off >>= 1)
        ss += __shfl_xor_sync(0xffffffffu, ss, off);
    __syncthreads();
    if ((tid & 31) == 0) red[tid >> 5] = ss;
    __syncthreads();
    float vtot = 0.f;
#pragma unroll
    for (int w = 0; w < 8; w++) vtot += red[w];
    const float inv = rsqrtf(vtot * (1.f / 1024.f) + 1e-5f);

    const float4 ga = ((const float4*)gamma)[tid];
    const float4 be = ((const float4*)beta)[tid];
    float4 o;
    o.x = ga.x * d0 * inv + be.x;
    o.y = ga.y * d1 * inv + be.y;
    o.z = ga.z * d2 * inv + be.z;
    o.w = ga.w * d3 * inv + be.w;
    ((float4*)(out + (size_t)row * D_SZ))[tid] = o;
}

// ---------------------------------------------------------------------------
extern "C" void kernel_launch(void* const* d_in, const int* in_sizes, int n_in,
                              void* d_out, int out_size)
{
    const float* Q     = (const float*)d_in[0];
    const float* K     = (const float*)d_in[1];
    const float* V     = (const float*)d_in[2];
    const int*   mask  = (const int*)  d_in[3];
    const float* Wq    = (const float*)d_in[4];
    const float* bq    = (const float*)d_in[5];
    const float* Wk    = (const float*)d_in[6];
    const float* bk    = (const float*)d_in[7];
    const float* Wv    = (const float*)d_in[8];
    const float* bv    = (const float*)d_in[9];
    const float* Wo    = (const float*)d_in[10];
    const float* bo    = (const float*)d_in[11];
    const float* gamma = (const float*)d_in[12];
    const float* beta  = (const float*)d_in[13];
    float* out = (float*)d_out;

    cudaFuncSetAttribute(flash_mma,
                         cudaFuncAttributeMaxDynamicSharedMemorySize,
                         FLASH_SMEM_B);
    cudaFuncSetAttribute(gemm_qkv,
                         cudaFuncAttributeMaxDynamicSharedMemorySize,
                         GEMM_SMEM_B);
    cudaFuncSetAttribute(gemm_o,
                         cudaFuncAttributeMaxDynamicSharedMemorySize,
                         GEMM_SMEM_B);
    (void)cudaGetLastError();

    const dim3 qkv_grid(D_SZ / 128, M_SZ / 128, 3);
    const dim3 o_grid(D_SZ / 128, M_SZ / 128);

    gemm_qkv<<<qkv_grid, 256, GEMM_SMEM_B>>>(Q, K, V, Wq, Wk, Wv, bq, bk, bv);

    flash_mma<<<dim3(S_SZ / 128, H_SZ, B_SZ), 256, FLASH_SMEM_B>>>(mask);

    gemm_o<<<o_grid, 256, GEMM_SMEM_B>>>(Wo, bo, Q);

    ln_kernel<<<M_SZ, 256>>>(gamma, beta, out);
}

// round 14
// speedup vs baseline: 4.9306x; 1.0203x over previous
#include <cuda_runtime.h>
#include <cstdint>
#include <cstddef>

// ---------------------------------------------------------------------------
// MultiHeadAttention fused block (round 13: resubmit 3-stage cp.async
// pipelines after broker-level container failure; source identical to
// round 12).
// ---------------------------------------------------------------------------

#define B_SZ   4
#define S_SZ   2048
#define D_SZ   1024
#define H_SZ   16
#define DH_SZ  64
#define M_SZ   (B_SZ * S_SZ)          // 8192

#define PK 68   // K/V pitch (words): 68 % 32 == 4 -> conflict-free everywhere
#define STAGE_W (128 * PK)            // 64 K rows + 64 V rows per stage
#define FLASH_SMEM_B (3 * STAGE_W * 4)      // 104448 B

#define GP 36                          // gemm smem pitch (36 % 32 == 4)
#define GSTAGE (128 * GP * 2)
#define GEMM_SMEM_B (3 * GSTAGE * 4)   // 110592 B

__device__ float g_q[M_SZ * D_SZ];
__device__ float g_k[M_SZ * D_SZ];
__device__ float g_v[M_SZ * D_SZ];
__device__ float g_ctx[M_SZ * D_SZ];

__device__ __forceinline__ uint32_t f2tf32(float x) {
    uint32_t r;
    asm("cvt.rna.tf32.f32 %0, %1;" : "=r"(r) : "f"(x));
    return r;
}

__device__ __forceinline__ void mma16n8k8(float c[4], const uint32_t a[4],
                                          const uint32_t b[2]) {
    asm volatile(
        "mma.sync.aligned.m16n8k8.row.col.f32.tf32.tf32.f32 "
        "{%0,%1,%2,%3}, {%4,%5,%6,%7}, {%8,%9}, {%0,%1,%2,%3};\n"
        : "+f"(c[0]), "+f"(c[1]), "+f"(c[2]), "+f"(c[3])
        : "r"(a[0]), "r"(a[1]), "r"(a[2]), "r"(a[3]), "r"(b[0]), "r"(b[1]));
}

__device__ __forceinline__ void cp16(uint32_t smem_dst, const void* gmem_src) {
    asm volatile("cp.async.cg.shared.global [%0], [%1], 16;\n"
                 :: "r"(smem_dst), "l"(gmem_src));
}

__device__ __forceinline__ void ldsm_x4(uint32_t d[4], uint32_t addr) {
    asm volatile("ldmatrix.sync.aligned.m8n8.x4.shared.b16 {%0,%1,%2,%3}, [%4];"
                 : "=r"(d[0]), "=r"(d[1]), "=r"(d[2]), "=r"(d[3]) : "r"(addr));
}

// ---------------------------------------------------------------------------
// Pipelined tf32 GEMM mainloop, 3-stage cp.async, ldmatrix fragment loads.
// One __syncthreads per k-tile: the barrier at iter t proves stage (t-1)%3
// was consumed, so tile t+2 is issued into it right after.
// ---------------------------------------------------------------------------
__device__ __forceinline__ void gemm_mainloop(
    const float* __restrict__ A, const float* __restrict__ W,
    int m0, int n0, uint32_t sbase, float acc[4][4][4])
{
    const int tid  = threadIdx.x;
    const int lane = tid & 31;
    const int warp = tid >> 5;
    const int wm   = (warp & 1) * 64;
    const int wn   = (warp >> 1) * 32;
    const int lm8  = lane & 7;
    const int m4   = lane >> 3;
    const int lr   = tid >> 3;
    const int lc   = (tid & 7) << 2;

#pragma unroll
    for (int mi = 0; mi < 4; mi++)
#pragma unroll
        for (int ni = 0; ni < 4; ni++)
#pragma unroll
            for (int c = 0; c < 4; c++) acc[mi][ni][c] = 0.f;

    auto issue = [&](int k0, int stage) {
        const uint32_t ab = sbase + (stage * GSTAGE) * 4;
        const uint32_t bb = ab + (128 * GP) * 4;
#pragma unroll
        for (int u = 0; u < 4; u++) {
            const int row = lr + 32 * u;
            cp16(ab + (row * GP + lc) * 4, A + (size_t)(m0 + row) * D_SZ + k0 + lc);
            cp16(bb + (row * GP + lc) * 4, W + (size_t)(n0 + row) * D_SZ + k0 + lc);
        }
        asm volatile("cp.async.commit_group;\n");
    };

    issue(0, 0);
    issue(32, 1);

    const int a_row = (m4 & 1) * 8 + lm8;
    const int a_col = (m4 >> 1) * 4;
    const int b_row = (m4 >> 1) * 8 + lm8;
    const int b_col = (m4 & 1) * 4;

    const int NK = D_SZ / 32;   // 32
    int s = 0;                  // stage of tile kt (cycles 0,1,2)
    for (int kt = 0; kt < NK; kt++) {
        if (kt + 1 < NK) asm volatile("cp.async.wait_group 1;\n");
        else             asm volatile("cp.async.wait_group 0;\n");
        __syncthreads();

        if (kt + 2 < NK) {
            int s2 = s + 2; if (s2 >= 3) s2 -= 3;   // == (kt-1)%3, consumed
            issue((kt + 2) * 32, s2);
        }

        const uint32_t aw = sbase + (s * GSTAGE) * 4;
        const uint32_t bw = aw + (128 * GP) * 4;

#pragma unroll
        for (int kk = 0; kk < 32; kk += 8) {
            uint32_t af[4][4], bf[4][2];
#pragma unroll
            for (int mi = 0; mi < 4; mi++)
                ldsm_x4(af[mi],
                        aw + ((wm + mi * 16 + a_row) * GP + kk + a_col) * 4);
#pragma unroll
            for (int np = 0; np < 4; np += 2)
                ldsm_x4(&bf[np][0],
                        bw + ((wn + np * 8 + b_row) * GP + kk + b_col) * 4);
#pragma unroll
            for (int mi = 0; mi < 4; mi++)
#pragma unroll
                for (int ni = 0; ni < 4; ni++)
                    mma16n8k8(acc[mi][ni], af[mi], bf[ni]);
        }

        if (++s == 3) s = 0;
    }
}

// ---------------------------------------------------------------------------
// Fused Q/K/V projection GEMM.
// ---------------------------------------------------------------------------
__global__ void __launch_bounds__(256, 2)
gemm_qkv(const float* __restrict__ Qin, const float* __restrict__ Kin,
         const float* __restrict__ Vin,
         const float* __restrict__ Wq, const float* __restrict__ Wk,
         const float* __restrict__ Wv,
         const float* __restrict__ bq, const float* __restrict__ bk,
         const float* __restrict__ bv)
{
    extern __shared__ uint32_t smbuf[];
    const uint32_t sbase = (uint32_t)__cvta_generic_to_shared(smbuf);

    const int mode = blockIdx.z;
    const float* A    = (mode == 0) ? Qin : (mode == 1) ? Kin : Vin;
    const float* W    = (mode == 0) ? Wq  : (mode == 1) ? Wk  : Wv;
    const float* bias = (mode == 0) ? bq  : (mode == 1) ? bk  : bv;
    float* out        = (mode == 0) ? g_q : (mode == 1) ? g_k : g_v;

    const int m0 = blockIdx.y * 128;
    const int n0 = blockIdx.x * 128;

    float acc[4][4][4];
    gemm_mainloop(A, W, m0, n0, sbase, acc);

    const int lane = threadIdx.x & 31;
    const int warp = threadIdx.x >> 5;
    const int wm = (warp & 1) * 64, wn = (warp >> 1) * 32;
    const int g = lane >> 2, tg = lane & 3;

#pragma unroll
    for (int mi = 0; mi < 4; mi++)
#pragma unroll
        for (int ni = 0; ni < 4; ni++)
#pragma unroll
            for (int h = 0; h < 2; h++) {
                const int m = m0 + wm + mi * 16 + g + h * 8;
                const int n = n0 + wn + ni * 8 + tg * 2;
                const int bI = m >> 11, s = m & 2047;
                const int head = n >> 6, dd = n & 63;
                float2 val;
                val.x = acc[mi][ni][h * 2 + 0] + bias[n];
                val.y = acc[mi][ni][h * 2 + 1] + bias[n + 1];
                *(float2*)&out[((size_t)(bI * H_SZ + head) << 17)
                               + ((size_t)s << 6) + dd] = val;
            }
}

// ---------------------------------------------------------------------------
// Output projection GEMM: x = g_ctx @ Wo^T + bo + resid -> g_q.
// ---------------------------------------------------------------------------
__global__ void __launch_bounds__(256, 2)
gemm_o(const float* __restrict__ Wo, const float* __restrict__ bo,
       const float* __restrict__ resid)
{
    extern __shared__ uint32_t smbuf[];
    const uint32_t sbase = (uint32_t)__cvta_generic_to_shared(smbuf);

    const int m0 = blockIdx.y * 128;
    const int n0 = blockIdx.x * 128;

    float acc[4][4][4];
    gemm_mainloop((const float*)g_ctx, Wo, m0, n0, sbase, acc);

    const int lane = threadIdx.x & 31;
    const int warp = threadIdx.x >> 5;
    const int wm = (warp & 1) * 64, wn = (warp >> 1) * 32;
    const int g = lane >> 2, tg = lane & 3;

#pragma unroll
    for (int mi = 0; mi < 4; mi++)
#pragma unroll
        for (int ni = 0; ni < 4; ni++)
#pragma unroll
            for (int h = 0; h < 2; h++) {
                const int m = m0 + wm + mi * 16 + g + h * 8;
                const int n = n0 + wn + ni * 8 + tg * 2;
                const size_t idx = (size_t)m * D_SZ + n;
                const float2 r2 = *(const float2*)&resid[idx];
                float2 val;
                val.x = acc[mi][ni][h * 2 + 0] + bo[n]     + r2.x;
                val.y = acc[mi][ni][h * 2 + 1] + bo[n + 1] + r2.y;
                *(float2*)&g_q[idx] = val;
            }
}

// ---------------------------------------------------------------------------
// Flash attention: tf32 mma, 3-stage cp.async KV pipeline, ldmatrix K-frags,
// zero-shuffle permuted-contraction PV (round 11).
// ---------------------------------------------------------------------------
__global__ void __launch_bounds__(256, 2)
flash_mma(const int* __restrict__ mask)
{
    extern __shared__ uint32_t smbuf[];

    const int b    = blockIdx.z;
    const int h    = blockIdx.y;
    const int q0   = blockIdx.x * 128;
    const int tid  = threadIdx.x;
    const int lane = tid & 31;
    const int warp = tid >> 5;
    const int g    = lane >> 2;
    const int tg   = lane & 3;
    const int lm8  = lane & 7;
    const int m4   = lane >> 3;

    const size_t bh = (size_t)(b * H_SZ + h) * (S_SZ * DH_SZ);
    const uint32_t sbase = (uint32_t)__cvta_generic_to_shared(smbuf);

    // Stage 128 Q rows (raw bits) into stage 0, extract frags, then recycle.
    {
        const float4* gq = (const float4*)(g_q + bh + (size_t)q0 * DH_SZ);
        for (int idx = tid; idx < 2048; idx += 256) {
            const int r = idx >> 4, c = (idx & 15) << 2;
            cp16(sbase + (r * PK + c) * 4, gq + idx);
        }
        asm volatile("cp.async.commit_group;\n");
        asm volatile("cp.async.wait_group 0;\n");
        __syncthreads();
    }

    uint32_t qf[8][4];
    {
        const int r = warp * 16 + g;
        const uint32_t* b0 = &smbuf[r * PK];
        const uint32_t* b1 = &smbuf[(r + 8) * PK];
#pragma unroll
        for (int k8 = 0; k8 < 8; k8++) {
            const int k = k8 * 8;
            qf[k8][0] = f2tf32(0.125f * __uint_as_float(b0[k + tg]));
            qf[k8][1] = f2tf32(0.125f * __uint_as_float(b1[k + tg]));
            qf[k8][2] = f2tf32(0.125f * __uint_as_float(b0[k + tg + 4]));
            qf[k8][3] = f2tf32(0.125f * __uint_as_float(b1[k + tg + 4]));
        }
    }
    __syncthreads();

    const float4* gkb = (const float4*)(g_k + bh);
    const float4* gvb = (const float4*)(g_v + bh);

    auto issue_tile = [&](int t, int stage) {
        const uint32_t kb = sbase + (stage * STAGE_W) * 4;
        const uint32_t vb = kb + (64 * PK) * 4;
        const float4* gk = gkb + (size_t)t * 1024;
        const float4* gv = gvb + (size_t)t * 1024;
#pragma unroll
        for (int u = 0; u < 4; u++) {
            const int idx = tid + 256 * u;
            const int r = idx >> 4, c = (idx & 15) << 2;
            cp16(kb + (r * PK + c) * 4, gk + idx);
            cp16(vb + (r * PK + c) * 4, gv + idx);
        }
        asm volatile("cp.async.commit_group;\n");
    };

    issue_tile(0, 0);
    issue_tile(1, 1);

    float of[8][4];
#pragma unroll
    for (int ni = 0; ni < 8; ni++)
#pragma unroll
        for (int c = 0; c < 4; c++) of[ni][c] = 0.f;
    float m0 = -1e30f, m1 = -1e30f, l0 = 0.f, l1 = 0.f;

    const int* mrow = mask + b * S_SZ;
    const int NT = S_SZ / 64;   // 32

    const int kq_col = (m4 >> 1) * 8 + (m4 & 1) * 4;

    int s = 0;   // stage of tile t (cycles 0,1,2)
    for (int t = 0; t < NT; t++) {
        if (t + 1 < NT) asm volatile("cp.async.wait_group 1;\n");
        else            asm volatile("cp.async.wait_group 0;\n");
        __syncthreads();

        if (t + 2 < NT) {
            int s2 = s + 2; if (s2 >= 3) s2 -= 3;   // consumed last iter
            issue_tile(t + 2, s2);
        }

        const uint32_t kwb = sbase + (s * STAGE_W) * 4;
        const uint32_t* VsS = &smbuf[s * STAGE_W + 64 * PK];

        // S = (Q/8) K^T
        float s_[8][4];
#pragma unroll
        for (int nt = 0; nt < 8; nt++) {
            s_[nt][0] = 0.f; s_[nt][1] = 0.f; s_[nt][2] = 0.f; s_[nt][3] = 0.f;
#pragma unroll
            for (int k8g = 0; k8g < 4; k8g++) {
                uint32_t d[4];
                ldsm_x4(d, kwb + ((nt * 8 + lm8) * PK + k8g * 16 + kq_col) * 4);
                mma16n8k8(s_[nt], qf[2 * k8g],     &d[0]);
                mma16n8k8(s_[nt], qf[2 * k8g + 1], &d[2]);
            }
        }

        // mask (additive), int2 loads
#pragma unroll
        for (int nt = 0; nt < 8; nt++) {
            const int2 mm = *(const int2*)&mrow[t * 64 + nt * 8 + tg * 2];
            const float ma = (mm.x == 0) ? -1e9f : 0.f;
            const float mb = (mm.y == 0) ? -1e9f : 0.f;
            s_[nt][0] += ma; s_[nt][1] += mb;
            s_[nt][2] += ma; s_[nt][3] += mb;
        }

        // online softmax: rows g (c0,c1) and g+8 (c2,c3), quad-lane reduce
        float rm0 = -1e30f, rm1 = -1e30f;
#pragma unroll
        for (int nt = 0; nt < 8; nt++) {
            rm0 = fmaxf(rm0, fmaxf(s_[nt][0], s_[nt][1]));
            rm1 = fmaxf(rm1, fmaxf(s_[nt][2], s_[nt][3]));
        }
        rm0 = fmaxf(rm0, __shfl_xor_sync(0xffffffffu, rm0, 1));
        rm0 = fmaxf(rm0, __shfl_xor_sync(0xffffffffu, rm0, 2));
        rm1 = fmaxf(rm1, __shfl_xor_sync(0xffffffffu, rm1, 1));
        rm1 = fmaxf(rm1, __shfl_xor_sync(0xffffffffu, rm1, 2));

        const float mn0 = fmaxf(m0, rm0);
        const float mn1 = fmaxf(m1, rm1);
        const float al0 = __expf(m0 - mn0);
        const float al1 = __expf(m1 - mn1);
        m0 = mn0; m1 = mn1;

        float rs0 = 0.f, rs1 = 0.f;
#pragma unroll
        for (int nt = 0; nt < 8; nt++) {
            s_[nt][0] = __expf(s_[nt][0] - mn0);
            s_[nt][1] = __expf(s_[nt][1] - mn0);
            s_[nt][2] = __expf(s_[nt][2] - mn1);
            s_[nt][3] = __expf(s_[nt][3] - mn1);
            rs0 += s_[nt][0] + s_[nt][1];
            rs1 += s_[nt][2] + s_[nt][3];
        }
        rs0 += __shfl_xor_sync(0xffffffffu, rs0, 1);
        rs0 += __shfl_xor_sync(0xffffffffu, rs0, 2);
        rs1 += __shfl_xor_sync(0xffffffffu, rs1, 1);
        rs1 += __shfl_xor_sync(0xffffffffu, rs1, 2);
        l0 = l0 * al0 + rs0;
        l1 = l1 * al1 + rs1;

#pragma unroll
        for (int ni = 0; ni < 8; ni++) {
            of[ni][0] *= al0; of[ni][1] *= al0;
            of[ni][2] *= al1; of[ni][3] *= al1;
        }

        // O += P V : permuted contraction, C-frag reused directly as A-frag
#pragma unroll
        for (int j = 0; j < 8; j++) {
            uint32_t pa[4];
            pa[0] = __float_as_uint(s_[j][0]);
            pa[1] = __float_as_uint(s_[j][2]);
            pa[2] = __float_as_uint(s_[j][1]);
            pa[3] = __float_as_uint(s_[j][3]);
            const uint32_t* vr0 = &VsS[(j * 8 + 2 * tg)     * PK];
            const uint32_t* vr1 = &VsS[(j * 8 + 2 * tg + 1) * PK];
#pragma unroll
            for (int ni = 0; ni < 8; ni++) {
                uint32_t bf[2];
                bf[0] = vr0[ni * 8 + g];
                bf[1] = vr1[ni * 8 + g];
                mma16n8k8(of[ni], pa, bf);
            }
        }

        if (++s == 3) s = 0;
    }

    const float il0 = 1.f / l0;
    const float il1 = 1.f / l1;
    const int row0 = b * S_SZ + q0 + warp * 16 + g;
    const int colb = h * DH_SZ;
#pragma unroll
    for (int ni = 0; ni < 8; ni++) {
        const int col = colb + ni * 8 + tg * 2;
        float2 v0, v1;
        v0.x = of[ni][0] * il0; v0.y = of[ni][1] * il0;
        v1.x = of[ni][2] * il1; v1.y = of[ni][3] * il1;
        *(float2*)&g_ctx[(size_t)row0 * D_SZ + col]       = v0;
        *(float2*)&g_ctx[(size_t)(row0 + 8) * D_SZ + col] = v1;
    }
}

// ---------------------------------------------------------------------------
// LayerNorm over last dim (1024). float4 vectorized, two-pass (exact).
// ---------------------------------------------------------------------------
__global__ void __launch_bounds__(256)
ln_kernel(const float* __restrict__ gamma, const float* __restrict__ beta,
          float* __restrict__ out)
{
    __shared__ float red[8];
    const int row = blockIdx.x;
    const int tid = threadIdx.x;
    const float4 v = ((const float4*)(g_q + (size_t)row * D_SZ))[tid];

    float s = v.x + v.y + v.z + v.w;
#pragma unroll
    for (int off = 16; off > 0; off >>= 1)
        s += __shfl_xor_sync(0xffffffffu, s, off);
    if ((tid & 31) == 0) red[tid >> 5] = s;
    __syncthreads();
    float tot = 0.f;
#pragma unroll
    for (int w = 0; w < 8; w++) tot += red[w];
    const float mu = tot * (1.f / 1024.f);

    const float d0 = v.x - mu, d1 = v.y - mu, d2 = v.z - mu, d3 = v.w - mu;
    float ss = d0 * d0 + d1 * d1 + d2 * d2 + d3 * d3;
#pragma unroll
    for (int off = 16; off > 0; off >>= 1)
        ss += __shfl_xor_sync(0xffffffffu, ss, off);
    __syncthreads();
    if ((tid & 31) == 0) red[tid >> 5] = ss;
    __syncthreads();
    float vtot = 0.f;
#pragma unroll
    for (int w = 0; w < 8; w++) vtot += red[w];
    const float inv = rsqrtf(vtot * (1.f / 1024.f) + 1e-5f);

    const float4 ga = ((const float4*)gamma)[tid];
    const float4 be = ((const float4*)beta)[tid];
    float4 o;
    o.x = ga.x * d0 * inv + be.x;
    o.y = ga.y * d1 * inv + be.y;
    o.z = ga.z * d2 * inv + be.z;
    o.w = ga.w * d3 * inv + be.w;
    ((float4*)(out + (size_t)row * D_SZ))[tid] = o;
}

// ---------------------------------------------------------------------------
extern "C" void kernel_launch(void* const* d_in, const int* in_sizes, int n_in,
                              void* d_out, int out_size)
{
    const float* Q     = (const float*)d_in[0];
    const float* K     = (const float*)d_in[1];
    const float* V     = (const float*)d_in[2];
    const int*   mask  = (const int*)  d_in[3];
    const float* Wq    = (const float*)d_in[4];
    const float* bq    = (const float*)d_in[5];
    const float* Wk    = (const float*)d_in[6];
    const float* bk    = (const float*)d_in[7];
    const float* Wv    = (const float*)d_in[8];
    const float* bv    = (const float*)d_in[9];
    const float* Wo    = (const float*)d_in[10];
    const float* bo    = (const float*)d_in[11];
    const float* gamma = (const float*)d_in[12];
    const float* beta  = (const float*)d_in[13];
    float* out = (float*)d_out;

    cudaFuncSetAttribute(flash_mma,
                         cudaFuncAttributeMaxDynamicSharedMemorySize,
                         FLASH_SMEM_B);
    cudaFuncSetAttribute(gemm_qkv,
                         cudaFuncAttributeMaxDynamicSharedMemorySize,
                         GEMM_SMEM_B);
    cudaFuncSetAttribute(gemm_o,
                         cudaFuncAttributeMaxDynamicSharedMemorySize,
                         GEMM_SMEM_B);
    (void)cudaGetLastError();

    const dim3 qkv_grid(D_SZ / 128, M_SZ / 128, 3);
    const dim3 o_grid(D_SZ / 128, M_SZ / 128);

    gemm_qkv<<<qkv_grid, 256, GEMM_SMEM_B>>>(Q, K, V, Wq, Wk, Wv, bq, bk, bv);

    flash_mma<<<dim3(S_SZ / 128, H_SZ, B_SZ), 256, FLASH_SMEM_B>>>(mask);

    gemm_o<<<o_grid, 256, GEMM_SMEM_B>>>(Wo, bo, Q);

    ln_kernel<<<M_SZ, 256>>>(gamma, beta, out);
}